// round 4
// baseline (speedup 1.0000x reference)
#include <cuda_runtime.h>
#include <math.h>
#include <stdint.h>

// Problem dims (fixed)
#define Bb   8
#define Ee   1024
#define Ss   2000
#define Hh   16
#define HDd  64
#define Mm   10
#define MLPn 4096
#define SEG  200      // Ss / Mm
#define BH   128      // Bb * Hh
#define LNEPS 1e-5f
#define QKSCALE 0.35355339059327373f   // 64^-0.25

// ---------------- scratch (static device memory; no allocation allowed) ----
__device__ float g_XT  [(size_t)Bb*Ss*Ee];      // (B,S,E)
__device__ float g_Q   [(size_t)BH*Ss*HDd];     // (B,H,S,HD) scaled
__device__ float g_K   [(size_t)BH*Ss*HDd];     // scaled
__device__ float g_V   [(size_t)BH*Ss*HDd];
__device__ float g_Ql  [BH*Mm*HDd];
__device__ float g_Kl  [BH*Mm*HDd];
__device__ float g_k2  [BH*Mm*Mm];
__device__ float g_k2inv[BH*Mm*Mm];
__device__ float g_normv;
__device__ float g_k3V [BH*Mm*HDd];
__device__ float g_coeff[(size_t)BH*Ss*Mm];     // k1 @ inv(k2)
__device__ float g_attn[(size_t)Bb*Ss*Ee];      // (B,S,E)
__device__ float g_h1  [(size_t)Bb*Ss*Ee];
__device__ float g_mid [(size_t)Bb*Ss*MLPn];
__device__ float g_h2  [(size_t)Bb*Ss*Ee];

// ---------------- transpose in: X (B,E,S) -> g_XT (B,S,E) ------------------
__global__ void k_transpose_in(const float* __restrict__ X) {
    __shared__ float t[32][33];
    int b = blockIdx.z;
    int s0 = blockIdx.x * 32, e0 = blockIdx.y * 32;
    int tx = threadIdx.x, ty = threadIdx.y;
#pragma unroll
    for (int i = 0; i < 4; i++) {
        int e = e0 + ty + i * 8, s = s0 + tx;
        if (s < Ss) t[ty + i * 8][tx] = X[((size_t)b * Ee + e) * Ss + s];
    }
    __syncthreads();
#pragma unroll
    for (int i = 0; i < 4; i++) {
        int s = s0 + ty + i * 8, e = e0 + tx;
        if (s < Ss) g_XT[((size_t)b * Ss + s) * Ee + e] = t[tx][ty + i * 8];
    }
}

// ---------------- transpose out: g_h1 (B,S,E) -> out (B,E,S) ---------------
__global__ void k_transpose_out(float* __restrict__ out) {
    __shared__ float t[32][33];
    int b = blockIdx.z;
    int e0 = blockIdx.x * 32, s0 = blockIdx.y * 32;
    int tx = threadIdx.x, ty = threadIdx.y;
#pragma unroll
    for (int i = 0; i < 4; i++) {
        int s = s0 + ty + i * 8, e = e0 + tx;
        if (s < Ss) t[ty + i * 8][tx] = g_h1[((size_t)b * Ss + s) * Ee + e];
    }
    __syncthreads();
#pragma unroll
    for (int i = 0; i < 4; i++) {
        int e = e0 + ty + i * 8, s = s0 + tx;
        if (s < Ss) out[((size_t)b * Ee + e) * Ss + s] = t[tx][ty + i * 8];
    }
}

// ===================== TF32 tensor-core NT GEMM ============================
// C = A(MxK) * W(NxK)^T + bias, tf32 mma.sync, fp32 accumulate.
// BM=128, BN=128, BK=32. 256 threads = 8 warps in 2(row)x4(col) grid,
// each warp computes 64x32 via 4x4 grid of m16n8k8 fragments.
// Fragment-order shared layout; double-buffered; 2 CTAs/SM forced.
#define TGEMM_SMEM (2 * (4096 + 4096) * 4)   // 64 KB (double buffered)

__device__ __forceinline__ uint32_t f2tf32(float f) {
    uint32_t u;
    asm("cvt.rna.tf32.f32 %0, %1;" : "=r"(u) : "f"(f));
    return u;
}

__global__ void __launch_bounds__(256, 2) k_tgemm(
    const float* __restrict__ A, const float* __restrict__ W,
    const float* __restrict__ bias, float* __restrict__ C,
    int Kdim, int Ndim, int mode, float scale)
{
    extern __shared__ uint32_t sm[];
    uint32_t* As = sm;             // [2][4096]
    uint32_t* Bs = sm + 2 * 4096;  // [2][4096]

    const int tid = threadIdx.x;
    const int lane = tid & 31, warp = tid >> 5;
    const int warpRow = warp >> 2, warpCol = warp & 3;
    const int g = lane >> 2, t4 = lane & 3;
    const size_t row0 = (size_t)blockIdx.x * 128;
    const size_t col0 = (size_t)blockIdx.y * 128;

    // loader per-thread geometry: 4 float4 loads, id = tid + i*256
    int lrow[4], lcol4[4], aoff[4], boff[4];
#pragma unroll
    for (int i = 0; i < 4; i++) {
        int id = tid + i * 256;
        int row = id >> 3, c4 = id & 7;
        lrow[i] = row; lcol4[i] = c4;
        int kstep = c4 >> 1, idx = c4 & 1;
        aoff[i] = ((kstep * 8 + (row >> 4)) * 32 + (row & 7) * 4) * 4
                  + ((row >> 3) & 1) + 2 * idx;
        boff[i] = ((kstep * 16 + (row >> 3)) * 32 + (row & 7) * 4) * 2 + idx;
    }

    float acc[4][4][4];
#pragma unroll
    for (int mf = 0; mf < 4; mf++)
#pragma unroll
        for (int nf = 0; nf < 4; nf++)
#pragma unroll
            for (int r = 0; r < 4; r++) acc[mf][nf][r] = 0.f;

    const int KT = Kdim >> 5;
    float4 ra[4], rb[4];

    // prologue: load K-tile 0
#pragma unroll
    for (int i = 0; i < 4; i++) {
        ra[i] = *(const float4*)(A + (row0 + lrow[i]) * Kdim + lcol4[i] * 4);
        rb[i] = *(const float4*)(W + (col0 + lrow[i]) * Kdim + lcol4[i] * 4);
    }
#pragma unroll
    for (int i = 0; i < 4; i++) {
        uint32_t* ap = As + aoff[i];
        ap[0]  = f2tf32(ra[i].x); ap[4]  = f2tf32(ra[i].y);
        ap[8]  = f2tf32(ra[i].z); ap[12] = f2tf32(ra[i].w);
        uint32_t* bp = Bs + boff[i];
        bp[0] = f2tf32(rb[i].x); bp[2] = f2tf32(rb[i].y);
        bp[4] = f2tf32(rb[i].z); bp[6] = f2tf32(rb[i].w);
    }
    __syncthreads();

    for (int kt = 0; kt < KT; kt++) {
        const int cur = kt & 1, nxt = cur ^ 1;
        const bool more = (kt + 1 < KT);
        if (more) {
            const float* Ap = A + (size_t)(kt + 1) * 32;
            const float* Wp = W + (size_t)(kt + 1) * 32;
#pragma unroll
            for (int i = 0; i < 4; i++) {
                ra[i] = *(const float4*)(Ap + (row0 + lrow[i]) * Kdim + lcol4[i] * 4);
                rb[i] = *(const float4*)(Wp + (col0 + lrow[i]) * Kdim + lcol4[i] * 4);
            }
        }
        const uint32_t* Ab = As + cur * 4096;
        const uint32_t* Bbuf = Bs + cur * 4096;
#pragma unroll
        for (int ks = 0; ks < 4; ks++) {
            uint4 af[4]; uint2 bf[4];
#pragma unroll
            for (int mf = 0; mf < 4; mf++)
                af[mf] = *(const uint4*)(Ab + ((ks * 8 + warpRow * 4 + mf) * 32 + lane) * 4);
#pragma unroll
            for (int nf = 0; nf < 4; nf++)
                bf[nf] = *(const uint2*)(Bbuf + ((ks * 16 + warpCol * 4 + nf) * 32 + lane) * 2);
#pragma unroll
            for (int mf = 0; mf < 4; mf++)
#pragma unroll
                for (int nf = 0; nf < 4; nf++) {
                    asm volatile(
                        "mma.sync.aligned.m16n8k8.row.col.f32.tf32.tf32.f32 "
                        "{%0,%1,%2,%3},{%4,%5,%6,%7},{%8,%9},{%0,%1,%2,%3};"
                        : "+f"(acc[mf][nf][0]), "+f"(acc[mf][nf][1]),
                          "+f"(acc[mf][nf][2]), "+f"(acc[mf][nf][3])
                        : "r"(af[mf].x), "r"(af[mf].y), "r"(af[mf].z), "r"(af[mf].w),
                          "r"(bf[nf].x), "r"(bf[nf].y));
                }
        }
        if (more) {
            uint32_t* Aw = As + nxt * 4096;
            uint32_t* Bw = Bs + nxt * 4096;
#pragma unroll
            for (int i = 0; i < 4; i++) {
                uint32_t* ap = Aw + aoff[i];
                ap[0]  = f2tf32(ra[i].x); ap[4]  = f2tf32(ra[i].y);
                ap[8]  = f2tf32(ra[i].z); ap[12] = f2tf32(ra[i].w);
                uint32_t* bp = Bw + boff[i];
                bp[0] = f2tf32(rb[i].x); bp[2] = f2tf32(rb[i].y);
                bp[4] = f2tf32(rb[i].z); bp[6] = f2tf32(rb[i].w);
            }
        }
        __syncthreads();
    }

    // ---- epilogue ----
#pragma unroll
    for (int mf = 0; mf < 4; mf++) {
#pragma unroll
        for (int h2 = 0; h2 < 2; h2++) {
            const size_t r = row0 + warpRow * 64 + mf * 16 + g + h2 * 8;
#pragma unroll
            for (int nf = 0; nf < 4; nf++) {
                const int c = (int)col0 + warpCol * 32 + nf * 8 + t4 * 2;
                float v0 = acc[mf][nf][h2 * 2 + 0] + bias[c];
                float v1 = acc[mf][nf][h2 * 2 + 1] + bias[c + 1];
                if (mode == 0) {
                    v0 *= scale; v1 *= scale;
                    int bb = (int)(r / Ss), s = (int)(r % Ss);
                    int h = c >> 6, d = c & 63;
                    float2* dst = (float2*)&C[(((size_t)(bb * Hh + h)) * Ss + s) * HDd + d];
                    *dst = make_float2(v0, v1);
                } else {
                    if (mode == 1) {
                        v0 = 0.5f * v0 * (1.f + erff(v0 * 0.7071067811865475f));
                        v1 = 0.5f * v1 * (1.f + erff(v1 * 0.7071067811865475f));
                    }
                    float2* dst = (float2*)&C[r * Ndim + c];
                    *dst = make_float2(v0, v1);
                }
            }
        }
    }
}

// ---------------- landmarks: segment means over 200 s ----------------------
__global__ void k_landmarks() {
    int bhm = blockIdx.x;
    int m = bhm % Mm, bh = bhm / Mm;
    int d = threadIdx.x;  // 64
    const float* Qb = g_Q + ((size_t)bh * Ss + m * SEG) * HDd + d;
    const float* Kb = g_K + ((size_t)bh * Ss + m * SEG) * HDd + d;
    float aq = 0.f, ak = 0.f;
    for (int j = 0; j < SEG; j++) { aq += Qb[(size_t)j * HDd]; ak += Kb[(size_t)j * HDd]; }
    g_Ql[(bh * Mm + m) * HDd + d] = aq * (1.f / SEG);
    g_Kl[(bh * Mm + m) * HDd + d] = ak * (1.f / SEG);
}

// ---------------- k2 = softmax(Ql @ Kl^T), per (b,h) -----------------------
__global__ void k_k2() {
    int bh = blockIdx.x;
    __shared__ float sQ[Mm * HDd], sK[Mm * HDd], sl[Mm][Mm];
    int t = threadIdx.x;  // 128
    for (int i = t; i < Mm * HDd; i += 128) {
        sQ[i] = g_Ql[bh * Mm * HDd + i];
        sK[i] = g_Kl[bh * Mm * HDd + i];
    }
    __syncthreads();
    if (t < 100) {
        int i = t / 10, j = t % 10;
        float s = 0.f;
#pragma unroll
        for (int d = 0; d < 64; d++) s += sQ[i * 64 + d] * sK[j * 64 + d];
        sl[i][j] = s;
    }
    __syncthreads();
    if (t < 100) {
        int i = t / 10, j = t % 10;
        float mx = -1e30f;
#pragma unroll
        for (int k = 0; k < 10; k++) mx = fmaxf(mx, sl[i][k]);
        float sum = 0.f;
#pragma unroll
        for (int k = 0; k < 10; k++) sum += expf(sl[i][k] - mx);
        g_k2[bh * 100 + t] = expf(sl[i][j] - mx) / sum;
    }
}

// ------- global normalization: max colsum(|k2|) * max rowsum(|k2|) --------
__global__ void k_norm() {
    __shared__ float rc[256], rr[256];
    int t = threadIdx.x;
    float mc = 0.f, mr = 0.f;
    for (int idx = t; idx < BH * Mm; idx += 256) {
        int bh = idx / Mm, j = idx % Mm;
        const float* Kp = g_k2 + bh * 100;
        float cs = 0.f, rs = 0.f;
#pragma unroll
        for (int i = 0; i < 10; i++) { cs += fabsf(Kp[i * 10 + j]); rs += fabsf(Kp[j * 10 + i]); }
        mc = fmaxf(mc, cs); mr = fmaxf(mr, rs);
    }
    rc[t] = mc; rr[t] = mr; __syncthreads();
    for (int o = 128; o > 0; o >>= 1) {
        if (t < o) { rc[t] = fmaxf(rc[t], rc[t + o]); rr[t] = fmaxf(rr[t], rr[t + o]); }
        __syncthreads();
    }
    if (t == 0) g_normv = rc[0] * rr[0];
}

// ---------------- Newton-Schulz iterative inverse of 10x10 k2 --------------
__global__ void k_inv() {
    int bh = blockIdx.x, t = threadIdx.x;  // 128 threads
    __shared__ float sK[100], sV[100], sKV[100], sA[100], sB2[100];
    if (t < 100) sK[t] = g_k2[bh * 100 + t];
    __syncthreads();
    float denom = g_normv;
    int i = t / 10, j = t % 10;
    if (t < 100) sV[t] = sK[j * 10 + i] / denom;
    __syncthreads();
    for (int it = 0; it < 6; it++) {
        if (t < 100) { float s = 0.f;
#pragma unroll
            for (int k = 0; k < 10; k++) s += sK[i * 10 + k] * sV[k * 10 + j];
            sKV[t] = s; }
        __syncthreads();
        if (t < 100) sA[t] = (i == j ? 7.f : 0.f) - sKV[t];
        __syncthreads();
        if (t < 100) { float s = 0.f;
#pragma unroll
            for (int k = 0; k < 10; k++) s += sKV[i * 10 + k] * sA[k * 10 + j];
            sB2[t] = (i == j ? 15.f : 0.f) - s; }
        __syncthreads();
        if (t < 100) { float s = 0.f;
#pragma unroll
            for (int k = 0; k < 10; k++) s += sKV[i * 10 + k] * sB2[k * 10 + j];
            sA[t] = (i == j ? 13.f : 0.f) - s; }
        __syncthreads();
        if (t < 100) { float s = 0.f;
#pragma unroll
            for (int k = 0; k < 10; k++) s += sV[i * 10 + k] * sA[k * 10 + j];
            sB2[t] = 0.25f * s; }
        __syncthreads();
        if (t < 100) sV[t] = sB2[t];
        __syncthreads();
    }
    if (t < 100) g_k2inv[bh * 100 + t] = sV[t];
}

// -------- fused k3 softmax (over S) @ V, all 10 landmarks per block --------
// one block per bh: K and V each read exactly once.
#define K3V_SMEM ((Mm * HDd + Mm * Ss + 4 * Mm * HDd) * 4)   // 92800 B
__global__ void __launch_bounds__(256) k_k3v2() {
    int bh = blockIdx.x;
    extern __shared__ float dyn[];
    float* sq   = dyn;                        // [10][64]
    float* lg   = dyn + Mm * HDd;             // [10][Ss] logits -> exp
    float* sout = dyn + Mm * HDd + Mm * Ss;   // [4][10][64]
    __shared__ float red[256];
    __shared__ float sinv[Mm];
    int t = threadIdx.x, lane = t & 31, w = t >> 5;
    for (int i = t; i < Mm * HDd; i += 256) sq[i] = g_Ql[bh * Mm * HDd + i];
    __syncthreads();
    // logits for all 10 landmarks, K read once
    for (int s = w; s < Ss; s += 8) {
        const float* Kr = g_K + ((size_t)bh * Ss + s) * 64;
        float ka = Kr[lane], kb = Kr[lane + 32];
#pragma unroll
        for (int m = 0; m < Mm; m++) {
            float p = ka * sq[m * 64 + lane] + kb * sq[m * 64 + lane + 32];
#pragma unroll
            for (int o = 16; o; o >>= 1) p += __shfl_xor_sync(0xffffffffu, p, o);
            if (lane == m) lg[m * Ss + s] = p;
        }
    }
    __syncthreads();
    // softmax over S per landmark
    for (int m = 0; m < Mm; m++) {
        float mx = -1e30f;
        for (int s = t; s < Ss; s += 256) mx = fmaxf(mx, lg[m * Ss + s]);
        red[t] = mx; __syncthreads();
        for (int o = 128; o; o >>= 1) { if (t < o) red[t] = fmaxf(red[t], red[t + o]); __syncthreads(); }
        mx = red[0]; __syncthreads();
        float sm = 0.f;
        for (int s = t; s < Ss; s += 256) { float e = expf(lg[m * Ss + s] - mx); lg[m * Ss + s] = e; sm += e; }
        red[t] = sm; __syncthreads();
        for (int o = 128; o; o >>= 1) { if (t < o) red[t] += red[t + o]; __syncthreads(); }
        if (t == 0) sinv[m] = 1.f / red[0];
        __syncthreads();
    }
    // V pass: V read once, accumulate all 10 outputs
    int d = t & 63, gg = t >> 6;
    float acc[Mm];
#pragma unroll
    for (int m = 0; m < Mm; m++) acc[m] = 0.f;
    for (int s = gg; s < Ss; s += 4) {
        float v = g_V[((size_t)bh * Ss + s) * 64 + d];
#pragma unroll
        for (int m = 0; m < Mm; m++) acc[m] += lg[m * Ss + s] * v;
    }
#pragma unroll
    for (int m = 0; m < Mm; m++) sout[(gg * Mm + m) * 64 + d] = acc[m];
    __syncthreads();
    for (int i = t; i < Mm * HDd; i += 256) {
        int m = i >> 6;
        float v = sout[i] + sout[Mm * 64 + i] + sout[2 * Mm * 64 + i] + sout[3 * Mm * 64 + i];
        g_k3V[bh * Mm * HDd + i] = v * sinv[m];
    }
}

// -------- coeff = softmax(Q @ Kl^T) @ inv(k2), per s -----------------------
__global__ void k_coeff() {
    int bh = blockIdx.x, t = threadIdx.x, lane = t & 31, w = t >> 5;
    __shared__ float sKl[Mm][64];
    __shared__ float sInv[100];
    for (int i = t; i < Mm * 64; i += 256) sKl[i / 64][i % 64] = g_Kl[bh * Mm * 64 + i];
    if (t < 100) sInv[t] = g_k2inv[bh * 100 + t];
    __syncthreads();
    for (int s = w; s < Ss; s += 8) {
        const float* Qr = g_Q + ((size_t)bh * Ss + s) * 64;
        float qa = Qr[lane], qb = Qr[lane + 32];
        float lg[10];
#pragma unroll
        for (int mm = 0; mm < 10; mm++) {
            float p = qa * sKl[mm][lane] + qb * sKl[mm][lane + 32];
#pragma unroll
            for (int o = 16; o; o >>= 1) p += __shfl_xor_sync(0xffffffffu, p, o);
            lg[mm] = p;
        }
        float mx = lg[0];
#pragma unroll
        for (int mm = 1; mm < 10; mm++) mx = fmaxf(mx, lg[mm]);
        float sum = 0.f;
#pragma unroll
        for (int mm = 0; mm < 10; mm++) { lg[mm] = expf(lg[mm] - mx); sum += lg[mm]; }
        float is = 1.f / sum;
        if (lane < 10) {
            float c = 0.f;
#pragma unroll
            for (int mm = 0; mm < 10; mm++) c += lg[mm] * sInv[mm * 10 + lane];
            g_coeff[((size_t)bh * Ss + s) * Mm + lane] = c * is;
        }
    }
}

// -------- attn[b,s,h*64+d] = coeff[s,:] @ k3V ------------------------------
__global__ void k_attn() {
    int bh = blockIdx.x;
    int s0 = blockIdx.y * 50;
    int b = bh / Hh, h = bh % Hh;
    __shared__ float sc[50][10];
    __shared__ float sw[10][64];
    int t = threadIdx.x;
    for (int i = t; i < 500; i += 256) sc[i / 10][i % 10] = g_coeff[((size_t)bh * Ss + s0) * Mm + i];
    for (int i = t; i < 640; i += 256) sw[i / 64][i % 64] = g_k3V[bh * Mm * 64 + i];
    __syncthreads();
    int d = t & 63, si0 = t >> 6;
    for (int si = si0; si < 50; si += 4) {
        float v = 0.f;
#pragma unroll
        for (int n = 0; n < 10; n++) v += sc[si][n] * sw[n][d];
        g_attn[((size_t)(b * Ss + s0 + si)) * Ee + h * 64 + d] = v;
    }
}

// -------- layernorm over last dim (E=1024), row per block ------------------
__global__ void k_ln(const float* __restrict__ x, const float* __restrict__ g,
                     const float* __restrict__ be, float* __restrict__ y) {
    int row = blockIdx.x, t = threadIdx.x;
    const float* xr = x + (size_t)row * Ee;
    __shared__ float r1[256], r2[256];
    float s = 0.f, ss = 0.f;
    for (int e = t; e < Ee; e += 256) { float v = xr[e]; s += v; ss += v * v; }
    r1[t] = s; r2[t] = ss; __syncthreads();
    for (int o = 128; o; o >>= 1) {
        if (t < o) { r1[t] += r1[t + o]; r2[t] += r2[t + o]; }
        __syncthreads();
    }
    float mu = r1[0] * (1.f / Ee);
    float var = r2[0] * (1.f / Ee) - mu * mu;
    float rstd = rsqrtf(var + LNEPS);
    for (int e = t; e < Ee; e += 256) {
        float v = xr[e];
        y[(size_t)row * Ee + e] = (v - mu) * rstd * g[e] + be[e];
    }
}

// ---------------------------------------------------------------------------
extern "C" void kernel_launch(void* const* d_in, const int* in_sizes, int n_in,
                              void* d_out, int out_size) {
    (void)in_sizes; (void)n_in; (void)out_size;
    const float* X   = (const float*)d_in[0];
    const float* Wq  = (const float*)d_in[1];
    const float* bq  = (const float*)d_in[2];
    const float* Wk  = (const float*)d_in[3];
    const float* bk  = (const float*)d_in[4];
    const float* Wv  = (const float*)d_in[5];
    const float* bv  = (const float*)d_in[6];
    const float* g1  = (const float*)d_in[7];
    const float* be1 = (const float*)d_in[8];
    const float* W1  = (const float*)d_in[9];
    const float* b1  = (const float*)d_in[10];
    const float* W2  = (const float*)d_in[11];
    const float* b2  = (const float*)d_in[12];
    const float* g2  = (const float*)d_in[13];
    const float* be2 = (const float*)d_in[14];
    float* out = (float*)d_out;

    float *pXT, *pQ, *pK, *pV, *pAttn, *pH1, *pMid, *pH2;
    cudaGetSymbolAddress((void**)&pXT,  g_XT);
    cudaGetSymbolAddress((void**)&pQ,   g_Q);
    cudaGetSymbolAddress((void**)&pK,   g_K);
    cudaGetSymbolAddress((void**)&pV,   g_V);
    cudaGetSymbolAddress((void**)&pAttn,g_attn);
    cudaGetSymbolAddress((void**)&pH1,  g_h1);
    cudaGetSymbolAddress((void**)&pMid, g_mid);
    cudaGetSymbolAddress((void**)&pH2,  g_h2);

    static int smem_set = 0;
    if (!smem_set) {
        cudaFuncSetAttribute(k_tgemm, cudaFuncAttributeMaxDynamicSharedMemorySize,
                             TGEMM_SMEM);
        cudaFuncSetAttribute(k_k3v2, cudaFuncAttributeMaxDynamicSharedMemorySize,
                             K3V_SMEM);
        smem_set = 1;
    }

    dim3 tb32(32, 8);
    // 1. X (B,E,S) -> XT (B,S,E)
    k_transpose_in<<<dim3((Ss + 31) / 32, Ee / 32, Bb), tb32>>>(X);
    // 2. QKV projections (tf32 tensor GEMM, M=16000, N=1024, K=1024)
    k_tgemm<<<dim3(125, 8), 256, TGEMM_SMEM>>>(pXT, Wq, bq, pQ, Ee, Hh * HDd, 0, QKSCALE);
    k_tgemm<<<dim3(125, 8), 256, TGEMM_SMEM>>>(pXT, Wk, bk, pK, Ee, Hh * HDd, 0, QKSCALE);
    k_tgemm<<<dim3(125, 8), 256, TGEMM_SMEM>>>(pXT, Wv, bv, pV, Ee, Hh * HDd, 0, 1.0f);
    // 3. landmarks
    k_landmarks<<<BH * Mm, 64>>>();
    // 4. k2 softmax
    k_k2<<<BH, 128>>>();
    // 5. global normalization scalar
    k_norm<<<1, 256>>>();
    // 6. 10x10 Newton inverse per (b,h)
    k_inv<<<BH, 128>>>();
    // 7. fused k3-softmax @ V (all landmarks per block; K,V read once)
    k_k3v2<<<BH, 256, K3V_SMEM>>>();
    // 8. coeff = softmax(Q Kl^T) @ inv
    k_coeff<<<BH, 256>>>();
    // 9. attn assembly -> (B,S,E)
    k_attn<<<dim3(BH, Ss / 50), 256>>>();
    // 10. LN1
    k_ln<<<Bb * Ss, 256>>>(pAttn, g1, be1, pH1);
    // 11. MLP1 + exact GELU (M=16000, N=4096, K=1024)
    k_tgemm<<<dim3(125, 32), 256, TGEMM_SMEM>>>(pH1, W1, b1, pMid, Ee, MLPn, 1, 1.0f);
    // 12. MLP2 (M=16000, N=1024, K=4096)
    k_tgemm<<<dim3(125, 8), 256, TGEMM_SMEM>>>(pMid, W2, b2, pH2, MLPn, Ee, 2, 1.0f);
    // 13. LN2 -> g_h1 (reuse)
    k_ln<<<Bb * Ss, 256>>>(pH2, g2, be2, pH1);
    // 14. (B,S,E) -> out (B,E,S)
    k_transpose_out<<<dim3(Ee / 32, (Ss + 31) / 32, Bb), tb32>>>(out);
}

// round 5
// speedup vs baseline: 1.0689x; 1.0689x over previous
#include <cuda_runtime.h>
#include <math.h>
#include <stdint.h>

// Problem dims (fixed)
#define Bb   8
#define Ee   1024
#define Ss   2000
#define Hh   16
#define HDd  64
#define Mm   10
#define MLPn 4096
#define SEG  200      // Ss / Mm
#define BH   128      // Bb * Hh
#define LNEPS 1e-5f
#define QKSCALE 0.35355339059327373f   // 64^-0.25

// ---------------- scratch (static device memory; no allocation allowed) ----
__device__ float g_XT  [(size_t)Bb*Ss*Ee];      // (B,S,E)
__device__ float g_Q   [(size_t)BH*Ss*HDd];     // (B,H,S,HD) scaled
__device__ float g_K   [(size_t)BH*Ss*HDd];     // scaled
__device__ float g_V   [(size_t)BH*Ss*HDd];
__device__ float g_Ql  [BH*Mm*HDd];
__device__ float g_Kl  [BH*Mm*HDd];
__device__ float g_k2  [BH*Mm*Mm];
__device__ float g_k2inv[BH*Mm*Mm];
__device__ float g_normv;
__device__ float g_k3V [BH*Mm*HDd];
__device__ float g_coeff[(size_t)BH*Ss*Mm];     // k1 @ inv(k2)
__device__ float g_attn[(size_t)Bb*Ss*Ee];      // (B,S,E)
__device__ float g_h1  [(size_t)Bb*Ss*Ee];
__device__ float g_mid [(size_t)Bb*Ss*MLPn];
__device__ float g_h2  [(size_t)Bb*Ss*Ee];

// ---------------- transpose in: X (B,E,S) -> g_XT (B,S,E) ------------------
__global__ void k_transpose_in(const float* __restrict__ X) {
    __shared__ float t[32][33];
    int b = blockIdx.z;
    int s0 = blockIdx.x * 32, e0 = blockIdx.y * 32;
    int tx = threadIdx.x, ty = threadIdx.y;
#pragma unroll
    for (int i = 0; i < 4; i++) {
        int e = e0 + ty + i * 8, s = s0 + tx;
        if (s < Ss) t[ty + i * 8][tx] = X[((size_t)b * Ee + e) * Ss + s];
    }
    __syncthreads();
#pragma unroll
    for (int i = 0; i < 4; i++) {
        int s = s0 + ty + i * 8, e = e0 + tx;
        if (s < Ss) g_XT[((size_t)b * Ss + s) * Ee + e] = t[tx][ty + i * 8];
    }
}

// ---------------- transpose out: g_h1 (B,S,E) -> out (B,E,S) ---------------
__global__ void k_transpose_out(float* __restrict__ out) {
    __shared__ float t[32][33];
    int b = blockIdx.z;
    int e0 = blockIdx.x * 32, s0 = blockIdx.y * 32;
    int tx = threadIdx.x, ty = threadIdx.y;
#pragma unroll
    for (int i = 0; i < 4; i++) {
        int s = s0 + ty + i * 8, e = e0 + tx;
        if (s < Ss) t[ty + i * 8][tx] = g_h1[((size_t)b * Ss + s) * Ee + e];
    }
    __syncthreads();
#pragma unroll
    for (int i = 0; i < 4; i++) {
        int e = e0 + ty + i * 8, s = s0 + tx;
        if (s < Ss) out[((size_t)b * Ee + e) * Ss + s] = t[tx][ty + i * 8];
    }
}

// ===================== TF32 tensor-core NT GEMM ============================
// C = A(MxK) * W(NxK)^T + bias, tf32 mma.sync, fp32 accumulate.
// BM=128, BN=64, BK=32. 256 threads = 8 warps in 4(row)x2(col) grid,
// each warp computes 32x32 via 2x4 grid of m16n8k8 fragments.
// Fragment-order shared layout (A frags: LDS.128, B frags: LDS.64),
// double-buffered. Small acc footprint -> ~100 regs -> 2 CTAs/SM naturally.
#define TGEMM_SMEM (2 * (4096 + 2048) * 4)   // 48 KB (double buffered)

__device__ __forceinline__ uint32_t f2tf32(float f) {
    uint32_t u;
    asm("cvt.rna.tf32.f32 %0, %1;" : "=r"(u) : "f"(f));
    return u;
}

__global__ void __launch_bounds__(256) k_tgemm(
    const float* __restrict__ A, const float* __restrict__ W,
    const float* __restrict__ bias, float* __restrict__ C,
    int Kdim, int Ndim, int mode, float scale)
{
    extern __shared__ uint32_t sm[];
    uint32_t* As = sm;             // [2][4096]
    uint32_t* Bs = sm + 2 * 4096;  // [2][2048]

    const int tid = threadIdx.x;
    const int lane = tid & 31, warp = tid >> 5;
    const int warpRow = warp >> 1, warpCol = warp & 1;   // 4 x 2
    const int g = lane >> 2, t4 = lane & 3;
    const size_t row0 = (size_t)blockIdx.x * 128;
    const size_t col0 = (size_t)blockIdx.y * 64;

    // A loader: 4 float4 per thread (128 rows x 8 col4)
    int larow[4], lacol4[4], aoff[4];
#pragma unroll
    for (int i = 0; i < 4; i++) {
        int id = tid + i * 256;
        int row = id >> 3, c4 = id & 7;
        larow[i] = row; lacol4[i] = c4;
        int kstep = c4 >> 1, idx = c4 & 1;
        aoff[i] = ((kstep * 8 + (row >> 4)) * 32 + (row & 7) * 4) * 4
                  + ((row >> 3) & 1) + 2 * idx;
    }
    // B loader: 2 float4 per thread (64 rows x 8 col4)
    int lbrow[2], lbcol4[2], boff[2];
#pragma unroll
    for (int i = 0; i < 2; i++) {
        int id = tid + i * 256;
        int row = id >> 3, c4 = id & 7;
        lbrow[i] = row; lbcol4[i] = c4;
        int kstep = c4 >> 1, idx = c4 & 1;
        boff[i] = ((kstep * 8 + (row >> 3)) * 32 + (row & 7) * 4) * 2 + idx;
    }

    float acc[2][4][4];
#pragma unroll
    for (int mf = 0; mf < 2; mf++)
#pragma unroll
        for (int nf = 0; nf < 4; nf++)
#pragma unroll
            for (int r = 0; r < 4; r++) acc[mf][nf][r] = 0.f;

    const int KT = Kdim >> 5;
    float4 ra[4], rb[2];

    // prologue: load K-tile 0
#pragma unroll
    for (int i = 0; i < 4; i++)
        ra[i] = *(const float4*)(A + (row0 + larow[i]) * Kdim + lacol4[i] * 4);
#pragma unroll
    for (int i = 0; i < 2; i++)
        rb[i] = *(const float4*)(W + (col0 + lbrow[i]) * Kdim + lbcol4[i] * 4);
#pragma unroll
    for (int i = 0; i < 4; i++) {
        uint32_t* ap = As + aoff[i];
        ap[0]  = f2tf32(ra[i].x); ap[4]  = f2tf32(ra[i].y);
        ap[8]  = f2tf32(ra[i].z); ap[12] = f2tf32(ra[i].w);
    }
#pragma unroll
    for (int i = 0; i < 2; i++) {
        uint32_t* bp = Bs + boff[i];
        bp[0] = f2tf32(rb[i].x); bp[2] = f2tf32(rb[i].y);
        bp[4] = f2tf32(rb[i].z); bp[6] = f2tf32(rb[i].w);
    }
    __syncthreads();

    for (int kt = 0; kt < KT; kt++) {
        const int cur = kt & 1, nxt = cur ^ 1;
        const bool more = (kt + 1 < KT);
        if (more) {
            const float* Ap = A + (size_t)(kt + 1) * 32;
            const float* Wp = W + (size_t)(kt + 1) * 32;
#pragma unroll
            for (int i = 0; i < 4; i++)
                ra[i] = *(const float4*)(Ap + (row0 + larow[i]) * Kdim + lacol4[i] * 4);
#pragma unroll
            for (int i = 0; i < 2; i++)
                rb[i] = *(const float4*)(Wp + (col0 + lbrow[i]) * Kdim + lbcol4[i] * 4);
        }
        const uint32_t* Ab = As + cur * 4096;
        const uint32_t* Bbuf = Bs + cur * 2048;
#pragma unroll
        for (int ks = 0; ks < 4; ks++) {
            uint4 af[2]; uint2 bf[4];
#pragma unroll
            for (int mf = 0; mf < 2; mf++)
                af[mf] = *(const uint4*)(Ab + ((ks * 8 + warpRow * 2 + mf) * 32 + lane) * 4);
#pragma unroll
            for (int nf = 0; nf < 4; nf++)
                bf[nf] = *(const uint2*)(Bbuf + ((ks * 8 + warpCol * 4 + nf) * 32 + lane) * 2);
#pragma unroll
            for (int mf = 0; mf < 2; mf++)
#pragma unroll
                for (int nf = 0; nf < 4; nf++) {
                    asm volatile(
                        "mma.sync.aligned.m16n8k8.row.col.f32.tf32.tf32.f32 "
                        "{%0,%1,%2,%3},{%4,%5,%6,%7},{%8,%9},{%0,%1,%2,%3};"
                        : "+f"(acc[mf][nf][0]), "+f"(acc[mf][nf][1]),
                          "+f"(acc[mf][nf][2]), "+f"(acc[mf][nf][3])
                        : "r"(af[mf].x), "r"(af[mf].y), "r"(af[mf].z), "r"(af[mf].w),
                          "r"(bf[nf].x), "r"(bf[nf].y));
                }
        }
        if (more) {
            uint32_t* Aw = As + nxt * 4096;
            uint32_t* Bw = Bs + nxt * 2048;
#pragma unroll
            for (int i = 0; i < 4; i++) {
                uint32_t* ap = Aw + aoff[i];
                ap[0]  = f2tf32(ra[i].x); ap[4]  = f2tf32(ra[i].y);
                ap[8]  = f2tf32(ra[i].z); ap[12] = f2tf32(ra[i].w);
            }
#pragma unroll
            for (int i = 0; i < 2; i++) {
                uint32_t* bp = Bw + boff[i];
                bp[0] = f2tf32(rb[i].x); bp[2] = f2tf32(rb[i].y);
                bp[4] = f2tf32(rb[i].z); bp[6] = f2tf32(rb[i].w);
            }
        }
        __syncthreads();
    }

    // ---- epilogue ----
#pragma unroll
    for (int mf = 0; mf < 2; mf++) {
#pragma unroll
        for (int h2 = 0; h2 < 2; h2++) {
            const size_t r = row0 + warpRow * 32 + mf * 16 + g + h2 * 8;
#pragma unroll
            for (int nf = 0; nf < 4; nf++) {
                const int c = (int)col0 + warpCol * 32 + nf * 8 + t4 * 2;
                float v0 = acc[mf][nf][h2 * 2 + 0] + bias[c];
                float v1 = acc[mf][nf][h2 * 2 + 1] + bias[c + 1];
                if (mode == 0) {
                    v0 *= scale; v1 *= scale;
                    int bb = (int)(r / Ss), s = (int)(r % Ss);
                    int h = c >> 6, d = c & 63;
                    float2* dst = (float2*)&C[(((size_t)(bb * Hh + h)) * Ss + s) * HDd + d];
                    *dst = make_float2(v0, v1);
                } else {
                    if (mode == 1) {
                        v0 = 0.5f * v0 * (1.f + erff(v0 * 0.7071067811865475f));
                        v1 = 0.5f * v1 * (1.f + erff(v1 * 0.7071067811865475f));
                    }
                    float2* dst = (float2*)&C[r * Ndim + c];
                    *dst = make_float2(v0, v1);
                }
            }
        }
    }
}

// ---------------- landmarks: segment means over 200 s ----------------------
__global__ void k_landmarks() {
    int bhm = blockIdx.x;
    int m = bhm % Mm, bh = bhm / Mm;
    int d = threadIdx.x;  // 64
    const float* Qb = g_Q + ((size_t)bh * Ss + m * SEG) * HDd + d;
    const float* Kb = g_K + ((size_t)bh * Ss + m * SEG) * HDd + d;
    float aq = 0.f, ak = 0.f;
    for (int j = 0; j < SEG; j++) { aq += Qb[(size_t)j * HDd]; ak += Kb[(size_t)j * HDd]; }
    g_Ql[(bh * Mm + m) * HDd + d] = aq * (1.f / SEG);
    g_Kl[(bh * Mm + m) * HDd + d] = ak * (1.f / SEG);
}

// ---------------- k2 = softmax(Ql @ Kl^T), per (b,h) -----------------------
__global__ void k_k2() {
    int bh = blockIdx.x;
    __shared__ float sQ[Mm * HDd], sK[Mm * HDd], sl[Mm][Mm];
    int t = threadIdx.x;  // 128
    for (int i = t; i < Mm * HDd; i += 128) {
        sQ[i] = g_Ql[bh * Mm * HDd + i];
        sK[i] = g_Kl[bh * Mm * HDd + i];
    }
    __syncthreads();
    if (t < 100) {
        int i = t / 10, j = t % 10;
        float s = 0.f;
#pragma unroll
        for (int d = 0; d < 64; d++) s += sQ[i * 64 + d] * sK[j * 64 + d];
        sl[i][j] = s;
    }
    __syncthreads();
    if (t < 100) {
        int i = t / 10, j = t % 10;
        float mx = -1e30f;
#pragma unroll
        for (int k = 0; k < 10; k++) mx = fmaxf(mx, sl[i][k]);
        float sum = 0.f;
#pragma unroll
        for (int k = 0; k < 10; k++) sum += expf(sl[i][k] - mx);
        g_k2[bh * 100 + t] = expf(sl[i][j] - mx) / sum;
    }
}

// ------- global normalization: max colsum(|k2|) * max rowsum(|k2|) --------
__global__ void k_norm() {
    __shared__ float rc[256], rr[256];
    int t = threadIdx.x;
    float mc = 0.f, mr = 0.f;
    for (int idx = t; idx < BH * Mm; idx += 256) {
        int bh = idx / Mm, j = idx % Mm;
        const float* Kp = g_k2 + bh * 100;
        float cs = 0.f, rs = 0.f;
#pragma unroll
        for (int i = 0; i < 10; i++) { cs += fabsf(Kp[i * 10 + j]); rs += fabsf(Kp[j * 10 + i]); }
        mc = fmaxf(mc, cs); mr = fmaxf(mr, rs);
    }
    rc[t] = mc; rr[t] = mr; __syncthreads();
    for (int o = 128; o > 0; o >>= 1) {
        if (t < o) { rc[t] = fmaxf(rc[t], rc[t + o]); rr[t] = fmaxf(rr[t], rr[t + o]); }
        __syncthreads();
    }
    if (t == 0) g_normv = rc[0] * rr[0];
}

// ---------------- Newton-Schulz iterative inverse of 10x10 k2 --------------
__global__ void k_inv() {
    int bh = blockIdx.x, t = threadIdx.x;  // 128 threads
    __shared__ float sK[100], sV[100], sKV[100], sA[100], sB2[100];
    if (t < 100) sK[t] = g_k2[bh * 100 + t];
    __syncthreads();
    float denom = g_normv;
    int i = t / 10, j = t % 10;
    if (t < 100) sV[t] = sK[j * 10 + i] / denom;
    __syncthreads();
    for (int it = 0; it < 6; it++) {
        if (t < 100) { float s = 0.f;
#pragma unroll
            for (int k = 0; k < 10; k++) s += sK[i * 10 + k] * sV[k * 10 + j];
            sKV[t] = s; }
        __syncthreads();
        if (t < 100) sA[t] = (i == j ? 7.f : 0.f) - sKV[t];
        __syncthreads();
        if (t < 100) { float s = 0.f;
#pragma unroll
            for (int k = 0; k < 10; k++) s += sKV[i * 10 + k] * sA[k * 10 + j];
            sB2[t] = (i == j ? 15.f : 0.f) - s; }
        __syncthreads();
        if (t < 100) { float s = 0.f;
#pragma unroll
            for (int k = 0; k < 10; k++) s += sKV[i * 10 + k] * sB2[k * 10 + j];
            sA[t] = (i == j ? 13.f : 0.f) - s; }
        __syncthreads();
        if (t < 100) { float s = 0.f;
#pragma unroll
            for (int k = 0; k < 10; k++) s += sV[i * 10 + k] * sA[k * 10 + j];
            sB2[t] = 0.25f * s; }
        __syncthreads();
        if (t < 100) sV[t] = sB2[t];
        __syncthreads();
    }
    if (t < 100) g_k2inv[bh * 100 + t] = sV[t];
}

// -------- fused k3 softmax (over S) @ V, all 10 landmarks per block --------
#define K3V_SMEM ((Mm * HDd + Mm * Ss + 4 * Mm * HDd) * 4)   // 92800 B
__global__ void __launch_bounds__(256) k_k3v2() {
    int bh = blockIdx.x;
    extern __shared__ float dyn[];
    float* sq   = dyn;                        // [10][64]
    float* lg   = dyn + Mm * HDd;             // [10][Ss] logits -> exp
    float* sout = dyn + Mm * HDd + Mm * Ss;   // [4][10][64]
    __shared__ float red[256];
    __shared__ float sinv[Mm];
    int t = threadIdx.x, lane = t & 31, w = t >> 5;
    for (int i = t; i < Mm * HDd; i += 256) sq[i] = g_Ql[bh * Mm * HDd + i];
    __syncthreads();
    for (int s = w; s < Ss; s += 8) {
        const float* Kr = g_K + ((size_t)bh * Ss + s) * 64;
        float ka = Kr[lane], kb = Kr[lane + 32];
#pragma unroll
        for (int m = 0; m < Mm; m++) {
            float p = ka * sq[m * 64 + lane] + kb * sq[m * 64 + lane + 32];
#pragma unroll
            for (int o = 16; o; o >>= 1) p += __shfl_xor_sync(0xffffffffu, p, o);
            if (lane == m) lg[m * Ss + s] = p;
        }
    }
    __syncthreads();
    for (int m = 0; m < Mm; m++) {
        float mx = -1e30f;
        for (int s = t; s < Ss; s += 256) mx = fmaxf(mx, lg[m * Ss + s]);
        red[t] = mx; __syncthreads();
        for (int o = 128; o; o >>= 1) { if (t < o) red[t] = fmaxf(red[t], red[t + o]); __syncthreads(); }
        mx = red[0]; __syncthreads();
        float sm = 0.f;
        for (int s = t; s < Ss; s += 256) { float e = expf(lg[m * Ss + s] - mx); lg[m * Ss + s] = e; sm += e; }
        red[t] = sm; __syncthreads();
        for (int o = 128; o; o >>= 1) { if (t < o) red[t] += red[t + o]; __syncthreads(); }
        if (t == 0) sinv[m] = 1.f / red[0];
        __syncthreads();
    }
    int d = t & 63, gg = t >> 6;
    float acc[Mm];
#pragma unroll
    for (int m = 0; m < Mm; m++) acc[m] = 0.f;
    for (int s = gg; s < Ss; s += 4) {
        float v = g_V[((size_t)bh * Ss + s) * 64 + d];
#pragma unroll
        for (int m = 0; m < Mm; m++) acc[m] += lg[m * Ss + s] * v;
    }
#pragma unroll
    for (int m = 0; m < Mm; m++) sout[(gg * Mm + m) * 64 + d] = acc[m];
    __syncthreads();
    for (int i = t; i < Mm * HDd; i += 256) {
        int m = i >> 6;
        float v = sout[i] + sout[Mm * 64 + i] + sout[2 * Mm * 64 + i] + sout[3 * Mm * 64 + i];
        g_k3V[bh * Mm * HDd + i] = v * sinv[m];
    }
}

// -------- coeff = softmax(Q @ Kl^T) @ inv(k2), per s -----------------------
__global__ void k_coeff() {
    int bh = blockIdx.x, t = threadIdx.x, lane = t & 31, w = t >> 5;
    __shared__ float sKl[Mm][64];
    __shared__ float sInv[100];
    for (int i = t; i < Mm * 64; i += 256) sKl[i / 64][i % 64] = g_Kl[bh * Mm * 64 + i];
    if (t < 100) sInv[t] = g_k2inv[bh * 100 + t];
    __syncthreads();
    for (int s = w; s < Ss; s += 8) {
        const float* Qr = g_Q + ((size_t)bh * Ss + s) * 64;
        float qa = Qr[lane], qb = Qr[lane + 32];
        float lg[10];
#pragma unroll
        for (int mm = 0; mm < 10; mm++) {
            float p = qa * sKl[mm][lane] + qb * sKl[mm][lane + 32];
#pragma unroll
            for (int o = 16; o; o >>= 1) p += __shfl_xor_sync(0xffffffffu, p, o);
            lg[mm] = p;
        }
        float mx = lg[0];
#pragma unroll
        for (int mm = 1; mm < 10; mm++) mx = fmaxf(mx, lg[mm]);
        float sum = 0.f;
#pragma unroll
        for (int mm = 0; mm < 10; mm++) { lg[mm] = expf(lg[mm] - mx); sum += lg[mm]; }
        float is = 1.f / sum;
        if (lane < 10) {
            float c = 0.f;
#pragma unroll
            for (int mm = 0; mm < 10; mm++) c += lg[mm] * sInv[mm * 10 + lane];
            g_coeff[((size_t)bh * Ss + s) * Mm + lane] = c * is;
        }
    }
}

// -------- attn[b,s,h*64+d] = coeff[s,:] @ k3V ------------------------------
__global__ void k_attn() {
    int bh = blockIdx.x;
    int s0 = blockIdx.y * 50;
    int b = bh / Hh, h = bh % Hh;
    __shared__ float sc[50][10];
    __shared__ float sw[10][64];
    int t = threadIdx.x;
    for (int i = t; i < 500; i += 256) sc[i / 10][i % 10] = g_coeff[((size_t)bh * Ss + s0) * Mm + i];
    for (int i = t; i < 640; i += 256) sw[i / 64][i % 64] = g_k3V[bh * Mm * 64 + i];
    __syncthreads();
    int d = t & 63, si0 = t >> 6;
    for (int si = si0; si < 50; si += 4) {
        float v = 0.f;
#pragma unroll
        for (int n = 0; n < 10; n++) v += sc[si][n] * sw[n][d];
        g_attn[((size_t)(b * Ss + s0 + si)) * Ee + h * 64 + d] = v;
    }
}

// -------- layernorm over last dim (E=1024), row per block ------------------
__global__ void k_ln(const float* __restrict__ x, const float* __restrict__ g,
                     const float* __restrict__ be, float* __restrict__ y) {
    int row = blockIdx.x, t = threadIdx.x;
    const float* xr = x + (size_t)row * Ee;
    __shared__ float r1[256], r2[256];
    float s = 0.f, ss = 0.f;
    for (int e = t; e < Ee; e += 256) { float v = xr[e]; s += v; ss += v * v; }
    r1[t] = s; r2[t] = ss; __syncthreads();
    for (int o = 128; o; o >>= 1) {
        if (t < o) { r1[t] += r1[t + o]; r2[t] += r2[t + o]; }
        __syncthreads();
    }
    float mu = r1[0] * (1.f / Ee);
    float var = r2[0] * (1.f / Ee) - mu * mu;
    float rstd = rsqrtf(var + LNEPS);
    for (int e = t; e < Ee; e += 256) {
        float v = xr[e];
        y[(size_t)row * Ee + e] = (v - mu) * rstd * g[e] + be[e];
    }
}

// ---------------------------------------------------------------------------
extern "C" void kernel_launch(void* const* d_in, const int* in_sizes, int n_in,
                              void* d_out, int out_size) {
    (void)in_sizes; (void)n_in; (void)out_size;
    const float* X   = (const float*)d_in[0];
    const float* Wq  = (const float*)d_in[1];
    const float* bq  = (const float*)d_in[2];
    const float* Wk  = (const float*)d_in[3];
    const float* bk  = (const float*)d_in[4];
    const float* Wv  = (const float*)d_in[5];
    const float* bv  = (const float*)d_in[6];
    const float* g1  = (const float*)d_in[7];
    const float* be1 = (const float*)d_in[8];
    const float* W1  = (const float*)d_in[9];
    const float* b1  = (const float*)d_in[10];
    const float* W2  = (const float*)d_in[11];
    const float* b2  = (const float*)d_in[12];
    const float* g2  = (const float*)d_in[13];
    const float* be2 = (const float*)d_in[14];
    float* out = (float*)d_out;

    float *pXT, *pQ, *pK, *pV, *pAttn, *pH1, *pMid, *pH2;
    cudaGetSymbolAddress((void**)&pXT,  g_XT);
    cudaGetSymbolAddress((void**)&pQ,   g_Q);
    cudaGetSymbolAddress((void**)&pK,   g_K);
    cudaGetSymbolAddress((void**)&pV,   g_V);
    cudaGetSymbolAddress((void**)&pAttn,g_attn);
    cudaGetSymbolAddress((void**)&pH1,  g_h1);
    cudaGetSymbolAddress((void**)&pMid, g_mid);
    cudaGetSymbolAddress((void**)&pH2,  g_h2);

    static int smem_set = 0;
    if (!smem_set) {
        cudaFuncSetAttribute(k_tgemm, cudaFuncAttributeMaxDynamicSharedMemorySize,
                             TGEMM_SMEM);
        cudaFuncSetAttribute(k_k3v2, cudaFuncAttributeMaxDynamicSharedMemorySize,
                             K3V_SMEM);
        smem_set = 1;
    }

    dim3 tb32(32, 8);
    // 1. X (B,E,S) -> XT (B,S,E)
    k_transpose_in<<<dim3((Ss + 31) / 32, Ee / 32, Bb), tb32>>>(X);
    // 2. QKV projections (tf32 tensor GEMM, M=16000, N=1024, K=1024)
    k_tgemm<<<dim3(125, 16), 256, TGEMM_SMEM>>>(pXT, Wq, bq, pQ, Ee, Hh * HDd, 0, QKSCALE);
    k_tgemm<<<dim3(125, 16), 256, TGEMM_SMEM>>>(pXT, Wk, bk, pK, Ee, Hh * HDd, 0, QKSCALE);
    k_tgemm<<<dim3(125, 16), 256, TGEMM_SMEM>>>(pXT, Wv, bv, pV, Ee, Hh * HDd, 0, 1.0f);
    // 3. landmarks
    k_landmarks<<<BH * Mm, 64>>>();
    // 4. k2 softmax
    k_k2<<<BH, 128>>>();
    // 5. global normalization scalar
    k_norm<<<1, 256>>>();
    // 6. 10x10 Newton inverse per (b,h)
    k_inv<<<BH, 128>>>();
    // 7. fused k3-softmax @ V (all landmarks per block; K,V read once)
    k_k3v2<<<BH, 256, K3V_SMEM>>>();
    // 8. coeff = softmax(Q Kl^T) @ inv
    k_coeff<<<BH, 256>>>();
    // 9. attn assembly -> (B,S,E)
    k_attn<<<dim3(BH, Ss / 50), 256>>>();
    // 10. LN1
    k_ln<<<Bb * Ss, 256>>>(pAttn, g1, be1, pH1);
    // 11. MLP1 + exact GELU (M=16000, N=4096, K=1024)
    k_tgemm<<<dim3(125, 64), 256, TGEMM_SMEM>>>(pH1, W1, b1, pMid, Ee, MLPn, 1, 1.0f);
    // 12. MLP2 (M=16000, N=1024, K=4096)
    k_tgemm<<<dim3(125, 16), 256, TGEMM_SMEM>>>(pMid, W2, b2, pH2, MLPn, Ee, 2, 1.0f);
    // 13. LN2 -> g_h1 (reuse)
    k_ln<<<Bb * Ss, 256>>>(pH2, g2, be2, pH1);
    // 14. (B,S,E) -> out (B,E,S)
    k_transpose_out<<<dim3(Ee / 32, (Ss + 31) / 32, Bb), tb32>>>(out);
}

// round 6
// speedup vs baseline: 1.3558x; 1.2684x over previous
#include <cuda_runtime.h>
#include <math.h>
#include <stdint.h>

// Problem dims (fixed)
#define Bb   8
#define Ee   1024
#define Ss   2000
#define Hh   16
#define HDd  64
#define Mm   10
#define MLPn 4096
#define SEG  200      // Ss / Mm
#define BH   128      // Bb * Hh
#define LNEPS 1e-5f
#define QKSCALE 0.35355339059327373f   // 64^-0.25

// ---------------- scratch (static device memory; no allocation allowed) ----
__device__ float g_XT  [(size_t)Bb*Ss*Ee];      // (B,S,E)
__device__ float g_Q   [(size_t)BH*Ss*HDd];     // (B,H,S,HD) scaled
__device__ float g_K   [(size_t)BH*Ss*HDd];     // scaled
__device__ float g_V   [(size_t)BH*Ss*HDd];
__device__ float g_Ql  [BH*Mm*HDd];
__device__ float g_Kl  [BH*Mm*HDd];
__device__ float g_k2  [BH*Mm*Mm];
__device__ float g_k2inv[BH*Mm*Mm];
__device__ float g_normv;
__device__ float g_k3V [BH*Mm*HDd];
__device__ float g_coeff[(size_t)BH*Ss*Mm];     // k1 @ inv(k2)
__device__ float g_attn[(size_t)Bb*Ss*Ee];      // (B,S,E)
__device__ float g_h1  [(size_t)Bb*Ss*Ee];
__device__ float g_mid [(size_t)Bb*Ss*MLPn];
__device__ float g_h2  [(size_t)Bb*Ss*Ee];

// ---------------- transpose in: X (B,E,S) -> g_XT (B,S,E) ------------------
__global__ void k_transpose_in(const float* __restrict__ X) {
    __shared__ float t[32][33];
    int b = blockIdx.z;
    int s0 = blockIdx.x * 32, e0 = blockIdx.y * 32;
    int tx = threadIdx.x, ty = threadIdx.y;
#pragma unroll
    for (int i = 0; i < 4; i++) {
        int e = e0 + ty + i * 8, s = s0 + tx;
        if (s < Ss) t[ty + i * 8][tx] = X[((size_t)b * Ee + e) * Ss + s];
    }
    __syncthreads();
#pragma unroll
    for (int i = 0; i < 4; i++) {
        int s = s0 + ty + i * 8, e = e0 + tx;
        if (s < Ss) g_XT[((size_t)b * Ss + s) * Ee + e] = t[tx][ty + i * 8];
    }
}

// ---------------- transpose out: g_h1 (B,S,E) -> out (B,E,S) ---------------
__global__ void k_transpose_out(float* __restrict__ out) {
    __shared__ float t[32][33];
    int b = blockIdx.z;
    int e0 = blockIdx.x * 32, s0 = blockIdx.y * 32;
    int tx = threadIdx.x, ty = threadIdx.y;
#pragma unroll
    for (int i = 0; i < 4; i++) {
        int s = s0 + ty + i * 8, e = e0 + tx;
        if (s < Ss) t[ty + i * 8][tx] = g_h1[((size_t)b * Ss + s) * Ee + e];
    }
    __syncthreads();
#pragma unroll
    for (int i = 0; i < 4; i++) {
        int e = e0 + ty + i * 8, s = s0 + tx;
        if (s < Ss) out[((size_t)b * Ee + e) * Ss + s] = t[tx][ty + i * 8];
    }
}

// ===================== TF32 tensor-core NT GEMM ============================
// C = A(MxK) * W(NxK)^T + bias, tf32 mma.sync, fp32 accumulate.
// BM=128, BN=128, BK=32. 512 threads = 16 warps in 4(row)x4(col) grid,
// each warp computes 32x32 via 2x4 grid of m16n8k8 fragments (32 acc regs).
// Fragment-order shared layout (A frags: LDS.128, B frags: LDS.64),
// double-buffered. ~95 regs, 16 resident warps in one CTA.
#define TGEMM_SMEM (2 * (4096 + 4096) * 4)   // 64 KB (double buffered)

__device__ __forceinline__ uint32_t f2tf32(float f) {
    uint32_t u;
    asm("cvt.rna.tf32.f32 %0, %1;" : "=r"(u) : "f"(f));
    return u;
}

__global__ void __launch_bounds__(512) k_tgemm(
    const float* __restrict__ A, const float* __restrict__ W,
    const float* __restrict__ bias, float* __restrict__ C,
    int Kdim, int Ndim, int mode, float scale)
{
    extern __shared__ uint32_t sm[];
    uint32_t* As = sm;             // [2][4096]
    uint32_t* Bs = sm + 2 * 4096;  // [2][4096]

    const int tid = threadIdx.x;
    const int lane = tid & 31, warp = tid >> 5;
    const int warpRow = warp >> 2, warpCol = warp & 3;   // 4 x 4
    const int g = lane >> 2, t4 = lane & 3;
    const size_t row0 = (size_t)blockIdx.x * 128;
    const size_t col0 = (size_t)blockIdx.y * 128;

    // loader: 2 float4 per thread for A and for B (128 rows x 8 col4 each)
    int lrow[2], lcol4[2], aoff[2], boff[2];
#pragma unroll
    for (int i = 0; i < 2; i++) {
        int id = tid + i * 512;
        int row = id >> 3, c4 = id & 7;
        lrow[i] = row; lcol4[i] = c4;
        int kstep = c4 >> 1, idx = c4 & 1;
        aoff[i] = ((kstep * 8 + (row >> 4)) * 32 + (row & 7) * 4) * 4
                  + ((row >> 3) & 1) + 2 * idx;
        boff[i] = ((kstep * 16 + (row >> 3)) * 32 + (row & 7) * 4) * 2 + idx;
    }

    float acc[2][4][4];
#pragma unroll
    for (int mf = 0; mf < 2; mf++)
#pragma unroll
        for (int nf = 0; nf < 4; nf++)
#pragma unroll
            for (int r = 0; r < 4; r++) acc[mf][nf][r] = 0.f;

    const int KT = Kdim >> 5;
    float4 ra[2], rb[2];

    // prologue: load K-tile 0
#pragma unroll
    for (int i = 0; i < 2; i++) {
        ra[i] = *(const float4*)(A + (row0 + lrow[i]) * Kdim + lcol4[i] * 4);
        rb[i] = *(const float4*)(W + (col0 + lrow[i]) * Kdim + lcol4[i] * 4);
    }
#pragma unroll
    for (int i = 0; i < 2; i++) {
        uint32_t* ap = As + aoff[i];
        ap[0]  = f2tf32(ra[i].x); ap[4]  = f2tf32(ra[i].y);
        ap[8]  = f2tf32(ra[i].z); ap[12] = f2tf32(ra[i].w);
        uint32_t* bp = Bs + boff[i];
        bp[0] = f2tf32(rb[i].x); bp[2] = f2tf32(rb[i].y);
        bp[4] = f2tf32(rb[i].z); bp[6] = f2tf32(rb[i].w);
    }
    __syncthreads();

    for (int kt = 0; kt < KT; kt++) {
        const int cur = kt & 1, nxt = cur ^ 1;
        const bool more = (kt + 1 < KT);
        if (more) {
            const float* Ap = A + (size_t)(kt + 1) * 32;
            const float* Wp = W + (size_t)(kt + 1) * 32;
#pragma unroll
            for (int i = 0; i < 2; i++) {
                ra[i] = *(const float4*)(Ap + (row0 + lrow[i]) * Kdim + lcol4[i] * 4);
                rb[i] = *(const float4*)(Wp + (col0 + lrow[i]) * Kdim + lcol4[i] * 4);
            }
        }
        const uint32_t* Ab = As + cur * 4096;
        const uint32_t* Bbuf = Bs + cur * 4096;
#pragma unroll
        for (int ks = 0; ks < 4; ks++) {
            uint4 af[2]; uint2 bf[4];
#pragma unroll
            for (int mf = 0; mf < 2; mf++)
                af[mf] = *(const uint4*)(Ab + ((ks * 8 + warpRow * 2 + mf) * 32 + lane) * 4);
#pragma unroll
            for (int nf = 0; nf < 4; nf++)
                bf[nf] = *(const uint2*)(Bbuf + ((ks * 16 + warpCol * 4 + nf) * 32 + lane) * 2);
#pragma unroll
            for (int mf = 0; mf < 2; mf++)
#pragma unroll
                for (int nf = 0; nf < 4; nf++) {
                    asm volatile(
                        "mma.sync.aligned.m16n8k8.row.col.f32.tf32.tf32.f32 "
                        "{%0,%1,%2,%3},{%4,%5,%6,%7},{%8,%9},{%0,%1,%2,%3};"
                        : "+f"(acc[mf][nf][0]), "+f"(acc[mf][nf][1]),
                          "+f"(acc[mf][nf][2]), "+f"(acc[mf][nf][3])
                        : "r"(af[mf].x), "r"(af[mf].y), "r"(af[mf].z), "r"(af[mf].w),
                          "r"(bf[nf].x), "r"(bf[nf].y));
                }
        }
        if (more) {
            uint32_t* Aw = As + nxt * 4096;
            uint32_t* Bw = Bs + nxt * 4096;
#pragma unroll
            for (int i = 0; i < 2; i++) {
                uint32_t* ap = Aw + aoff[i];
                ap[0]  = f2tf32(ra[i].x); ap[4]  = f2tf32(ra[i].y);
                ap[8]  = f2tf32(ra[i].z); ap[12] = f2tf32(ra[i].w);
                uint32_t* bp = Bw + boff[i];
                bp[0] = f2tf32(rb[i].x); bp[2] = f2tf32(rb[i].y);
                bp[4] = f2tf32(rb[i].z); bp[6] = f2tf32(rb[i].w);
            }
        }
        __syncthreads();
    }

    // ---- epilogue ----
#pragma unroll
    for (int mf = 0; mf < 2; mf++) {
#pragma unroll
        for (int h2 = 0; h2 < 2; h2++) {
            const size_t r = row0 + warpRow * 32 + mf * 16 + g + h2 * 8;
#pragma unroll
            for (int nf = 0; nf < 4; nf++) {
                const int c = (int)col0 + warpCol * 32 + nf * 8 + t4 * 2;
                float v0 = acc[mf][nf][h2 * 2 + 0] + bias[c];
                float v1 = acc[mf][nf][h2 * 2 + 1] + bias[c + 1];
                if (mode == 0) {
                    v0 *= scale; v1 *= scale;
                    int bb = (int)(r / Ss), s = (int)(r % Ss);
                    int h = c >> 6, d = c & 63;
                    float2* dst = (float2*)&C[(((size_t)(bb * Hh + h)) * Ss + s) * HDd + d];
                    *dst = make_float2(v0, v1);
                } else {
                    if (mode == 1) {
                        v0 = 0.5f * v0 * (1.f + erff(v0 * 0.7071067811865475f));
                        v1 = 0.5f * v1 * (1.f + erff(v1 * 0.7071067811865475f));
                    }
                    float2* dst = (float2*)&C[r * Ndim + c];
                    *dst = make_float2(v0, v1);
                }
            }
        }
    }
}

// ---------------- landmarks: segment means over 200 s ----------------------
__global__ void k_landmarks() {
    int bhm = blockIdx.x;
    int m = bhm % Mm, bh = bhm / Mm;
    int d = threadIdx.x;  // 64
    const float* Qb = g_Q + ((size_t)bh * Ss + m * SEG) * HDd + d;
    const float* Kb = g_K + ((size_t)bh * Ss + m * SEG) * HDd + d;
    float aq = 0.f, ak = 0.f;
    for (int j = 0; j < SEG; j++) { aq += Qb[(size_t)j * HDd]; ak += Kb[(size_t)j * HDd]; }
    g_Ql[(bh * Mm + m) * HDd + d] = aq * (1.f / SEG);
    g_Kl[(bh * Mm + m) * HDd + d] = ak * (1.f / SEG);
}

// ---------------- k2 = softmax(Ql @ Kl^T), per (b,h) -----------------------
__global__ void k_k2() {
    int bh = blockIdx.x;
    __shared__ float sQ[Mm * HDd], sK[Mm * HDd], sl[Mm][Mm];
    int t = threadIdx.x;  // 128
    for (int i = t; i < Mm * HDd; i += 128) {
        sQ[i] = g_Ql[bh * Mm * HDd + i];
        sK[i] = g_Kl[bh * Mm * HDd + i];
    }
    __syncthreads();
    if (t < 100) {
        int i = t / 10, j = t % 10;
        float s = 0.f;
#pragma unroll
        for (int d = 0; d < 64; d++) s += sQ[i * 64 + d] * sK[j * 64 + d];
        sl[i][j] = s;
    }
    __syncthreads();
    if (t < 100) {
        int i = t / 10, j = t % 10;
        float mx = -1e30f;
#pragma unroll
        for (int k = 0; k < 10; k++) mx = fmaxf(mx, sl[i][k]);
        float sum = 0.f;
#pragma unroll
        for (int k = 0; k < 10; k++) sum += expf(sl[i][k] - mx);
        g_k2[bh * 100 + t] = expf(sl[i][j] - mx) / sum;
    }
}

// ------- global normalization: max colsum(|k2|) * max rowsum(|k2|) --------
__global__ void k_norm() {
    __shared__ float rc[256], rr[256];
    int t = threadIdx.x;
    float mc = 0.f, mr = 0.f;
    for (int idx = t; idx < BH * Mm; idx += 256) {
        int bh = idx / Mm, j = idx % Mm;
        const float* Kp = g_k2 + bh * 100;
        float cs = 0.f, rs = 0.f;
#pragma unroll
        for (int i = 0; i < 10; i++) { cs += fabsf(Kp[i * 10 + j]); rs += fabsf(Kp[j * 10 + i]); }
        mc = fmaxf(mc, cs); mr = fmaxf(mr, rs);
    }
    rc[t] = mc; rr[t] = mr; __syncthreads();
    for (int o = 128; o > 0; o >>= 1) {
        if (t < o) { rc[t] = fmaxf(rc[t], rc[t + o]); rr[t] = fmaxf(rr[t], rr[t + o]); }
        __syncthreads();
    }
    if (t == 0) g_normv = rc[0] * rr[0];
}

// ---------------- Newton-Schulz iterative inverse of 10x10 k2 --------------
__global__ void k_inv() {
    int bh = blockIdx.x, t = threadIdx.x;  // 128 threads
    __shared__ float sK[100], sV[100], sKV[100], sA[100], sB2[100];
    if (t < 100) sK[t] = g_k2[bh * 100 + t];
    __syncthreads();
    float denom = g_normv;
    int i = t / 10, j = t % 10;
    if (t < 100) sV[t] = sK[j * 10 + i] / denom;
    __syncthreads();
    for (int it = 0; it < 6; it++) {
        if (t < 100) { float s = 0.f;
#pragma unroll
            for (int k = 0; k < 10; k++) s += sK[i * 10 + k] * sV[k * 10 + j];
            sKV[t] = s; }
        __syncthreads();
        if (t < 100) sA[t] = (i == j ? 7.f : 0.f) - sKV[t];
        __syncthreads();
        if (t < 100) { float s = 0.f;
#pragma unroll
            for (int k = 0; k < 10; k++) s += sKV[i * 10 + k] * sA[k * 10 + j];
            sB2[t] = (i == j ? 15.f : 0.f) - s; }
        __syncthreads();
        if (t < 100) { float s = 0.f;
#pragma unroll
            for (int k = 0; k < 10; k++) s += sKV[i * 10 + k] * sB2[k * 10 + j];
            sA[t] = (i == j ? 13.f : 0.f) - s; }
        __syncthreads();
        if (t < 100) { float s = 0.f;
#pragma unroll
            for (int k = 0; k < 10; k++) s += sV[i * 10 + k] * sA[k * 10 + j];
            sB2[t] = 0.25f * s; }
        __syncthreads();
        if (t < 100) sV[t] = sB2[t];
        __syncthreads();
    }
    if (t < 100) g_k2inv[bh * 100 + t] = sV[t];
}

// -------- fused k3 softmax (over S) @ V, all 10 landmarks per block --------
#define K3V_SMEM ((Mm * HDd + Mm * Ss + 4 * Mm * HDd) * 4)   // 92800 B
__global__ void __launch_bounds__(256) k_k3v2() {
    int bh = blockIdx.x;
    extern __shared__ float dyn[];
    float* sq   = dyn;                        // [10][64]
    float* lg   = dyn + Mm * HDd;             // [10][Ss] logits -> exp
    float* sout = dyn + Mm * HDd + Mm * Ss;   // [4][10][64]
    __shared__ float red[256];
    __shared__ float sinv[Mm];
    int t = threadIdx.x, lane = t & 31, w = t >> 5;
    for (int i = t; i < Mm * HDd; i += 256) sq[i] = g_Ql[bh * Mm * HDd + i];
    __syncthreads();
    for (int s = w; s < Ss; s += 8) {
        const float* Kr = g_K + ((size_t)bh * Ss + s) * 64;
        float ka = Kr[lane], kb = Kr[lane + 32];
#pragma unroll
        for (int m = 0; m < Mm; m++) {
            float p = ka * sq[m * 64 + lane] + kb * sq[m * 64 + lane + 32];
#pragma unroll
            for (int o = 16; o; o >>= 1) p += __shfl_xor_sync(0xffffffffu, p, o);
            if (lane == m) lg[m * Ss + s] = p;
        }
    }
    __syncthreads();
    for (int m = 0; m < Mm; m++) {
        float mx = -1e30f;
        for (int s = t; s < Ss; s += 256) mx = fmaxf(mx, lg[m * Ss + s]);
        red[t] = mx; __syncthreads();
        for (int o = 128; o; o >>= 1) { if (t < o) red[t] = fmaxf(red[t], red[t + o]); __syncthreads(); }
        mx = red[0]; __syncthreads();
        float sm = 0.f;
        for (int s = t; s < Ss; s += 256) { float e = expf(lg[m * Ss + s] - mx); lg[m * Ss + s] = e; sm += e; }
        red[t] = sm; __syncthreads();
        for (int o = 128; o; o >>= 1) { if (t < o) red[t] += red[t + o]; __syncthreads(); }
        if (t == 0) sinv[m] = 1.f / red[0];
        __syncthreads();
    }
    int d = t & 63, gg = t >> 6;
    float acc[Mm];
#pragma unroll
    for (int m = 0; m < Mm; m++) acc[m] = 0.f;
    for (int s = gg; s < Ss; s += 4) {
        float v = g_V[((size_t)bh * Ss + s) * 64 + d];
#pragma unroll
        for (int m = 0; m < Mm; m++) acc[m] += lg[m * Ss + s] * v;
    }
#pragma unroll
    for (int m = 0; m < Mm; m++) sout[(gg * Mm + m) * 64 + d] = acc[m];
    __syncthreads();
    for (int i = t; i < Mm * HDd; i += 256) {
        int m = i >> 6;
        float v = sout[i] + sout[Mm * 64 + i] + sout[2 * Mm * 64 + i] + sout[3 * Mm * 64 + i];
        g_k3V[bh * Mm * HDd + i] = v * sinv[m];
    }
}

// -------- coeff = softmax(Q @ Kl^T) @ inv(k2), per s -----------------------
__global__ void k_coeff() {
    int bh = blockIdx.x, t = threadIdx.x, lane = t & 31, w = t >> 5;
    __shared__ float sKl[Mm][64];
    __shared__ float sInv[100];
    for (int i = t; i < Mm * 64; i += 256) sKl[i / 64][i % 64] = g_Kl[bh * Mm * 64 + i];
    if (t < 100) sInv[t] = g_k2inv[bh * 100 + t];
    __syncthreads();
    for (int s = w; s < Ss; s += 8) {
        const float* Qr = g_Q + ((size_t)bh * Ss + s) * 64;
        float qa = Qr[lane], qb = Qr[lane + 32];
        float lg[10];
#pragma unroll
        for (int mm = 0; mm < 10; mm++) {
            float p = qa * sKl[mm][lane] + qb * sKl[mm][lane + 32];
#pragma unroll
            for (int o = 16; o; o >>= 1) p += __shfl_xor_sync(0xffffffffu, p, o);
            lg[mm] = p;
        }
        float mx = lg[0];
#pragma unroll
        for (int mm = 1; mm < 10; mm++) mx = fmaxf(mx, lg[mm]);
        float sum = 0.f;
#pragma unroll
        for (int mm = 0; mm < 10; mm++) { lg[mm] = expf(lg[mm] - mx); sum += lg[mm]; }
        float is = 1.f / sum;
        if (lane < 10) {
            float c = 0.f;
#pragma unroll
            for (int mm = 0; mm < 10; mm++) c += lg[mm] * sInv[mm * 10 + lane];
            g_coeff[((size_t)bh * Ss + s) * Mm + lane] = c * is;
        }
    }
}

// -------- attn[b,s,h*64+d] = coeff[s,:] @ k3V ------------------------------
__global__ void k_attn() {
    int bh = blockIdx.x;
    int s0 = blockIdx.y * 50;
    int b = bh / Hh, h = bh % Hh;
    __shared__ float sc[50][10];
    __shared__ float sw[10][64];
    int t = threadIdx.x;
    for (int i = t; i < 500; i += 256) sc[i / 10][i % 10] = g_coeff[((size_t)bh * Ss + s0) * Mm + i];
    for (int i = t; i < 640; i += 256) sw[i / 64][i % 64] = g_k3V[bh * Mm * 64 + i];
    __syncthreads();
    int d = t & 63, si0 = t >> 6;
    for (int si = si0; si < 50; si += 4) {
        float v = 0.f;
#pragma unroll
        for (int n = 0; n < 10; n++) v += sc[si][n] * sw[n][d];
        g_attn[((size_t)(b * Ss + s0 + si)) * Ee + h * 64 + d] = v;
    }
}

// -------- layernorm over last dim (E=1024), row per block ------------------
__global__ void k_ln(const float* __restrict__ x, const float* __restrict__ g,
                     const float* __restrict__ be, float* __restrict__ y) {
    int row = blockIdx.x, t = threadIdx.x;
    const float* xr = x + (size_t)row * Ee;
    __shared__ float r1[256], r2[256];
    float s = 0.f, ss = 0.f;
    for (int e = t; e < Ee; e += 256) { float v = xr[e]; s += v; ss += v * v; }
    r1[t] = s; r2[t] = ss; __syncthreads();
    for (int o = 128; o; o >>= 1) {
        if (t < o) { r1[t] += r1[t + o]; r2[t] += r2[t + o]; }
        __syncthreads();
    }
    float mu = r1[0] * (1.f / Ee);
    float var = r2[0] * (1.f / Ee) - mu * mu;
    float rstd = rsqrtf(var + LNEPS);
    for (int e = t; e < Ee; e += 256) {
        float v = xr[e];
        y[(size_t)row * Ee + e] = (v - mu) * rstd * g[e] + be[e];
    }
}

// ---------------------------------------------------------------------------
extern "C" void kernel_launch(void* const* d_in, const int* in_sizes, int n_in,
                              void* d_out, int out_size) {
    (void)in_sizes; (void)n_in; (void)out_size;
    const float* X   = (const float*)d_in[0];
    const float* Wq  = (const float*)d_in[1];
    const float* bq  = (const float*)d_in[2];
    const float* Wk  = (const float*)d_in[3];
    const float* bk  = (const float*)d_in[4];
    const float* Wv  = (const float*)d_in[5];
    const float* bv  = (const float*)d_in[6];
    const float* g1  = (const float*)d_in[7];
    const float* be1 = (const float*)d_in[8];
    const float* W1  = (const float*)d_in[9];
    const float* b1  = (const float*)d_in[10];
    const float* W2  = (const float*)d_in[11];
    const float* b2  = (const float*)d_in[12];
    const float* g2  = (const float*)d_in[13];
    const float* be2 = (const float*)d_in[14];
    float* out = (float*)d_out;

    float *pXT, *pQ, *pK, *pV, *pAttn, *pH1, *pMid, *pH2;
    cudaGetSymbolAddress((void**)&pXT,  g_XT);
    cudaGetSymbolAddress((void**)&pQ,   g_Q);
    cudaGetSymbolAddress((void**)&pK,   g_K);
    cudaGetSymbolAddress((void**)&pV,   g_V);
    cudaGetSymbolAddress((void**)&pAttn,g_attn);
    cudaGetSymbolAddress((void**)&pH1,  g_h1);
    cudaGetSymbolAddress((void**)&pMid, g_mid);
    cudaGetSymbolAddress((void**)&pH2,  g_h2);

    static int smem_set = 0;
    if (!smem_set) {
        cudaFuncSetAttribute(k_tgemm, cudaFuncAttributeMaxDynamicSharedMemorySize,
                             TGEMM_SMEM);
        cudaFuncSetAttribute(k_k3v2, cudaFuncAttributeMaxDynamicSharedMemorySize,
                             K3V_SMEM);
        smem_set = 1;
    }

    dim3 tb32(32, 8);
    // 1. X (B,E,S) -> XT (B,S,E)
    k_transpose_in<<<dim3((Ss + 31) / 32, Ee / 32, Bb), tb32>>>(X);
    // 2. QKV projections (tf32 tensor GEMM, M=16000, N=1024, K=1024)
    k_tgemm<<<dim3(125, 8), 512, TGEMM_SMEM>>>(pXT, Wq, bq, pQ, Ee, Hh * HDd, 0, QKSCALE);
    k_tgemm<<<dim3(125, 8), 512, TGEMM_SMEM>>>(pXT, Wk, bk, pK, Ee, Hh * HDd, 0, QKSCALE);
    k_tgemm<<<dim3(125, 8), 512, TGEMM_SMEM>>>(pXT, Wv, bv, pV, Ee, Hh * HDd, 0, 1.0f);
    // 3. landmarks
    k_landmarks<<<BH * Mm, 64>>>();
    // 4. k2 softmax
    k_k2<<<BH, 128>>>();
    // 5. global normalization scalar
    k_norm<<<1, 256>>>();
    // 6. 10x10 Newton inverse per (b,h)
    k_inv<<<BH, 128>>>();
    // 7. fused k3-softmax @ V (all landmarks per block; K,V read once)
    k_k3v2<<<BH, 256, K3V_SMEM>>>();
    // 8. coeff = softmax(Q Kl^T) @ inv
    k_coeff<<<BH, 256>>>();
    // 9. attn assembly -> (B,S,E)
    k_attn<<<dim3(BH, Ss / 50), 256>>>();
    // 10. LN1
    k_ln<<<Bb * Ss, 256>>>(pAttn, g1, be1, pH1);
    // 11. MLP1 + exact GELU (M=16000, N=4096, K=1024)
    k_tgemm<<<dim3(125, 32), 512, TGEMM_SMEM>>>(pH1, W1, b1, pMid, Ee, MLPn, 1, 1.0f);
    // 12. MLP2 (M=16000, N=1024, K=4096)
    k_tgemm<<<dim3(125, 8), 512, TGEMM_SMEM>>>(pMid, W2, b2, pH2, MLPn, Ee, 2, 1.0f);
    // 13. LN2 -> g_h1 (reuse)
    k_ln<<<Bb * Ss, 256>>>(pH2, g2, be2, pH1);
    // 14. (B,S,E) -> out (B,E,S)
    k_transpose_out<<<dim3(Ee / 32, (Ss + 31) / 32, Bb), tb32>>>(out);
}

// round 8
// speedup vs baseline: 1.8805x; 1.3870x over previous
#include <cuda_runtime.h>
#include <cuda_fp16.h>
#include <math.h>
#include <stdint.h>

// Problem dims (fixed)
#define Bb   8
#define Ee   1024
#define Ss   2000
#define Hh   16
#define HDd  64
#define Mm   10
#define MLPn 4096
#define SEG  200      // Ss / Mm
#define BH   128      // Bb * Hh
#define LNEPS 1e-5f
#define QKSCALE 0.35355339059327373f   // 64^-0.25

// ---------------- scratch (static device memory; no allocation allowed) ----
__device__ float g_XT  [(size_t)Bb*Ss*Ee];      // (B,S,E)
__device__ float g_Q   [(size_t)BH*Ss*HDd];     // (B,H,S,HD) scaled
__device__ float g_K   [(size_t)BH*Ss*HDd];     // scaled
__device__ float g_V   [(size_t)BH*Ss*HDd];
__device__ float g_Ql  [BH*Mm*HDd];
__device__ float g_Kl  [BH*Mm*HDd];
__device__ float g_k2  [BH*Mm*Mm];
__device__ float g_k2inv[BH*Mm*Mm];
__device__ float g_normv;
__device__ float g_k3V [BH*Mm*HDd];
__device__ float g_coeff[(size_t)BH*Ss*Mm];     // k1 @ inv(k2)
__device__ float g_attn[(size_t)Bb*Ss*Ee];      // (B,S,E)
__device__ float g_h1  [(size_t)Bb*Ss*Ee];
__device__ float g_mid [(size_t)Bb*Ss*MLPn];
__device__ float g_h2  [(size_t)Bb*Ss*Ee];

// ---------------- transpose in: X (B,E,S) -> g_XT (B,S,E) ------------------
__global__ void k_transpose_in(const float* __restrict__ X) {
    __shared__ float t[32][33];
    int b = blockIdx.z;
    int s0 = blockIdx.x * 32, e0 = blockIdx.y * 32;
    int tx = threadIdx.x, ty = threadIdx.y;
#pragma unroll
    for (int i = 0; i < 4; i++) {
        int e = e0 + ty + i * 8, s = s0 + tx;
        if (s < Ss) t[ty + i * 8][tx] = X[((size_t)b * Ee + e) * Ss + s];
    }
    __syncthreads();
#pragma unroll
    for (int i = 0; i < 4; i++) {
        int s = s0 + ty + i * 8, e = e0 + tx;
        if (s < Ss) g_XT[((size_t)b * Ss + s) * Ee + e] = t[tx][ty + i * 8];
    }
}

// ---------------- transpose out: g_h1 (B,S,E) -> out (B,E,S) ---------------
__global__ void k_transpose_out(float* __restrict__ out) {
    __shared__ float t[32][33];
    int b = blockIdx.z;
    int e0 = blockIdx.x * 32, s0 = blockIdx.y * 32;
    int tx = threadIdx.x, ty = threadIdx.y;
#pragma unroll
    for (int i = 0; i < 4; i++) {
        int s = s0 + ty + i * 8, e = e0 + tx;
        if (s < Ss) t[ty + i * 8][tx] = g_h1[((size_t)b * Ss + s) * Ee + e];
    }
    __syncthreads();
#pragma unroll
    for (int i = 0; i < 4; i++) {
        int e = e0 + ty + i * 8, s = s0 + tx;
        if (s < Ss) out[((size_t)b * Ee + e) * Ss + s] = t[tx][ty + i * 8];
    }
}

// ===================== FP16 tensor-core NT GEMM ============================
// C = A(MxK) * W(NxK)^T + bias; inputs rounded to fp16 (11-bit significand,
// same as tf32), fp32 accumulate via mma.sync m16n8k16.
// BM=BN=128, BK=32. 512 threads = 16 warps in 4x4 grid, warp tile 32x32
// (2 mfrag x 4 nfrag, 2 k16-steps per K-tile -> 16 MMA/warp/tile).
// Fragment-order smem: A frags LDS.128, B frags LDS.64. Double buffered.
#define TGEMM_SMEM (4 * 2048 * 4)   // 32 KB

__global__ void __launch_bounds__(512) k_tgemm(
    const float* __restrict__ A, const float* __restrict__ W,
    const float* __restrict__ bias, float* __restrict__ C,
    int Kdim, int Ndim, int mode, float scale)
{
    extern __shared__ uint32_t sm[];
    uint32_t* As = sm;             // [2][2048] b32 (each = half2)
    uint32_t* Bs = sm + 2 * 2048;  // [2][2048]

    const int tid = threadIdx.x;
    const int lane = tid & 31, warp = tid >> 5;
    const int warpRow = warp >> 2, warpCol = warp & 3;   // 4 x 4
    const int g = lane >> 2, t4c = lane & 3;
    const size_t row0 = (size_t)blockIdx.x * 128;
    const size_t col0 = (size_t)blockIdx.y * 128;

    // loader geometry: 2 float4 each for A and B; idx = tid + i*512
    // row = idx>>3, c4 = idx&7 (k0 = c4*4)
    int lrow[2], lc4[2], aoff[2], boff[2];
#pragma unroll
    for (int i = 0; i < 2; i++) {
        int idx = tid + i * 512;
        int row = idx >> 3, c4 = idx & 7;
        lrow[i] = row; lc4[i] = c4;
        int ks = c4 >> 2, q = c4 & 3;
        int t4 = (q & 1) * 2;    // q:0->0,1->2,2->0,3->2
        int hi = q >> 1;
        int gg = row & 7, rh = (row >> 3) & 1;
        aoff[i] = ((ks * 8 + (row >> 4)) * 32 + gg * 4 + t4) * 4 + hi * 2 + rh;
        boff[i] = ((ks * 16 + (row >> 3)) * 32 + gg * 4 + t4) * 2 + hi;
    }

    float acc[2][4][4];
#pragma unroll
    for (int mf = 0; mf < 2; mf++)
#pragma unroll
        for (int nf = 0; nf < 4; nf++)
#pragma unroll
            for (int r = 0; r < 4; r++) acc[mf][nf][r] = 0.f;

    const int KT = Kdim >> 5;
    float4 ra[2], rb[2];

    // prologue: stage K-tile 0
#pragma unroll
    for (int i = 0; i < 2; i++) {
        ra[i] = *(const float4*)(A + (row0 + lrow[i]) * Kdim + lc4[i] * 4);
        rb[i] = *(const float4*)(W + (col0 + lrow[i]) * Kdim + lc4[i] * 4);
    }
#pragma unroll
    for (int i = 0; i < 2; i++) {
        __half2 a01 = __floats2half2_rn(ra[i].x, ra[i].y);
        __half2 a23 = __floats2half2_rn(ra[i].z, ra[i].w);
        As[aoff[i]]     = *(uint32_t*)&a01;
        As[aoff[i] + 4] = *(uint32_t*)&a23;   // next t4 -> +4 b32
        __half2 b01 = __floats2half2_rn(rb[i].x, rb[i].y);
        __half2 b23 = __floats2half2_rn(rb[i].z, rb[i].w);
        Bs[boff[i]]     = *(uint32_t*)&b01;
        Bs[boff[i] + 2] = *(uint32_t*)&b23;   // next t4 -> +2 b32
    }
    __syncthreads();

    for (int kt = 0; kt < KT; kt++) {
        const int cur = kt & 1, nxt = cur ^ 1;
        const bool more = (kt + 1 < KT);
        if (more) {
            const float* Ap = A + (size_t)(kt + 1) * 32;
            const float* Wp = W + (size_t)(kt + 1) * 32;
#pragma unroll
            for (int i = 0; i < 2; i++) {
                ra[i] = *(const float4*)(Ap + (row0 + lrow[i]) * Kdim + lc4[i] * 4);
                rb[i] = *(const float4*)(Wp + (col0 + lrow[i]) * Kdim + lc4[i] * 4);
            }
        }
        const uint32_t* Ab = As + cur * 2048;
        const uint32_t* Bbuf = Bs + cur * 2048;
#pragma unroll
        for (int ks = 0; ks < 2; ks++) {
            uint4 af[2]; uint2 bf[4];
#pragma unroll
            for (int mf = 0; mf < 2; mf++)
                af[mf] = *(const uint4*)(Ab + ((ks * 8 + warpRow * 2 + mf) * 32 + lane) * 4);
#pragma unroll
            for (int nf = 0; nf < 4; nf++)
                bf[nf] = *(const uint2*)(Bbuf + ((ks * 16 + warpCol * 4 + nf) * 32 + lane) * 2);
#pragma unroll
            for (int mf = 0; mf < 2; mf++)
#pragma unroll
                for (int nf = 0; nf < 4; nf++) {
                    asm volatile(
                        "mma.sync.aligned.m16n8k16.row.col.f32.f16.f16.f32 "
                        "{%0,%1,%2,%3},{%4,%5,%6,%7},{%8,%9},{%0,%1,%2,%3};"
                        : "+f"(acc[mf][nf][0]), "+f"(acc[mf][nf][1]),
                          "+f"(acc[mf][nf][2]), "+f"(acc[mf][nf][3])
                        : "r"(af[mf].x), "r"(af[mf].y), "r"(af[mf].z), "r"(af[mf].w),
                          "r"(bf[nf].x), "r"(bf[nf].y));
                }
        }
        if (more) {
            uint32_t* Aw = As + nxt * 2048;
            uint32_t* Bw = Bs + nxt * 2048;
#pragma unroll
            for (int i = 0; i < 2; i++) {
                __half2 a01 = __floats2half2_rn(ra[i].x, ra[i].y);
                __half2 a23 = __floats2half2_rn(ra[i].z, ra[i].w);
                Aw[aoff[i]]     = *(uint32_t*)&a01;
                Aw[aoff[i] + 4] = *(uint32_t*)&a23;
                __half2 b01 = __floats2half2_rn(rb[i].x, rb[i].y);
                __half2 b23 = __floats2half2_rn(rb[i].z, rb[i].w);
                Bw[boff[i]]     = *(uint32_t*)&b01;
                Bw[boff[i] + 2] = *(uint32_t*)&b23;
            }
        }
        __syncthreads();
    }

    // ---- epilogue ----
#pragma unroll
    for (int mf = 0; mf < 2; mf++) {
#pragma unroll
        for (int h2 = 0; h2 < 2; h2++) {
            const size_t r = row0 + warpRow * 32 + mf * 16 + g + h2 * 8;
#pragma unroll
            for (int nf = 0; nf < 4; nf++) {
                const int c = (int)col0 + warpCol * 32 + nf * 8 + t4c * 2;
                float v0 = acc[mf][nf][h2 * 2 + 0] + bias[c];
                float v1 = acc[mf][nf][h2 * 2 + 1] + bias[c + 1];
                if (mode == 0) {
                    v0 *= scale; v1 *= scale;
                    int bb = (int)(r / Ss), s = (int)(r % Ss);
                    int h = c >> 6, d = c & 63;
                    float2* dst = (float2*)&C[(((size_t)(bb * Hh + h)) * Ss + s) * HDd + d];
                    *dst = make_float2(v0, v1);
                } else {
                    if (mode == 1) {
                        v0 = 0.5f * v0 * (1.f + erff(v0 * 0.7071067811865475f));
                        v1 = 0.5f * v1 * (1.f + erff(v1 * 0.7071067811865475f));
                    }
                    float2* dst = (float2*)&C[r * Ndim + c];
                    *dst = make_float2(v0, v1);
                }
            }
        }
    }
}

// ---------------- landmarks: segment means over 200 s ----------------------
__global__ void k_landmarks() {
    int bhm = blockIdx.x;
    int m = bhm % Mm, bh = bhm / Mm;
    int d = threadIdx.x;  // 64
    const float* Qb = g_Q + ((size_t)bh * Ss + m * SEG) * HDd + d;
    const float* Kb = g_K + ((size_t)bh * Ss + m * SEG) * HDd + d;
    float aq = 0.f, ak = 0.f;
    for (int j = 0; j < SEG; j++) { aq += Qb[(size_t)j * HDd]; ak += Kb[(size_t)j * HDd]; }
    g_Ql[(bh * Mm + m) * HDd + d] = aq * (1.f / SEG);
    g_Kl[(bh * Mm + m) * HDd + d] = ak * (1.f / SEG);
}

// ---------------- k2 = softmax(Ql @ Kl^T), per (b,h) -----------------------
__global__ void k_k2() {
    int bh = blockIdx.x;
    __shared__ float sQ[Mm * HDd], sK[Mm * HDd], sl[Mm][Mm];
    int t = threadIdx.x;  // 128
    for (int i = t; i < Mm * HDd; i += 128) {
        sQ[i] = g_Ql[bh * Mm * HDd + i];
        sK[i] = g_Kl[bh * Mm * HDd + i];
    }
    __syncthreads();
    if (t < 100) {
        int i = t / 10, j = t % 10;
        float s = 0.f;
#pragma unroll
        for (int d = 0; d < 64; d++) s += sQ[i * 64 + d] * sK[j * 64 + d];
        sl[i][j] = s;
    }
    __syncthreads();
    if (t < 100) {
        int i = t / 10, j = t % 10;
        float mx = -1e30f;
#pragma unroll
        for (int k = 0; k < 10; k++) mx = fmaxf(mx, sl[i][k]);
        float sum = 0.f;
#pragma unroll
        for (int k = 0; k < 10; k++) sum += expf(sl[i][k] - mx);
        g_k2[bh * 100 + t] = expf(sl[i][j] - mx) / sum;
    }
}

// ------- global normalization: max colsum(|k2|) * max rowsum(|k2|) --------
__global__ void k_norm() {
    __shared__ float rc[256], rr[256];
    int t = threadIdx.x;
    float mc = 0.f, mr = 0.f;
    for (int idx = t; idx < BH * Mm; idx += 256) {
        int bh = idx / Mm, j = idx % Mm;
        const float* Kp = g_k2 + bh * 100;
        float cs = 0.f, rs = 0.f;
#pragma unroll
        for (int i = 0; i < 10; i++) { cs += fabsf(Kp[i * 10 + j]); rs += fabsf(Kp[j * 10 + i]); }
        mc = fmaxf(mc, cs); mr = fmaxf(mr, rs);
    }
    rc[t] = mc; rr[t] = mr; __syncthreads();
    for (int o = 128; o > 0; o >>= 1) {
        if (t < o) { rc[t] = fmaxf(rc[t], rc[t + o]); rr[t] = fmaxf(rr[t], rr[t + o]); }
        __syncthreads();
    }
    if (t == 0) g_normv = rc[0] * rr[0];
}

// ---------------- Newton-Schulz iterative inverse of 10x10 k2 --------------
__global__ void k_inv() {
    int bh = blockIdx.x, t = threadIdx.x;  // 128 threads
    __shared__ float sK[100], sV[100], sKV[100], sA[100], sB2[100];
    if (t < 100) sK[t] = g_k2[bh * 100 + t];
    __syncthreads();
    float denom = g_normv;
    int i = t / 10, j = t % 10;
    if (t < 100) sV[t] = sK[j * 10 + i] / denom;
    __syncthreads();
    for (int it = 0; it < 6; it++) {
        if (t < 100) { float s = 0.f;
#pragma unroll
            for (int k = 0; k < 10; k++) s += sK[i * 10 + k] * sV[k * 10 + j];
            sKV[t] = s; }
        __syncthreads();
        if (t < 100) sA[t] = (i == j ? 7.f : 0.f) - sKV[t];
        __syncthreads();
        if (t < 100) { float s = 0.f;
#pragma unroll
            for (int k = 0; k < 10; k++) s += sKV[i * 10 + k] * sA[k * 10 + j];
            sB2[t] = (i == j ? 15.f : 0.f) - s; }
        __syncthreads();
        if (t < 100) { float s = 0.f;
#pragma unroll
            for (int k = 0; k < 10; k++) s += sKV[i * 10 + k] * sB2[k * 10 + j];
            sA[t] = (i == j ? 13.f : 0.f) - s; }
        __syncthreads();
        if (t < 100) { float s = 0.f;
#pragma unroll
            for (int k = 0; k < 10; k++) s += sV[i * 10 + k] * sA[k * 10 + j];
            sB2[t] = 0.25f * s; }
        __syncthreads();
        if (t < 100) sV[t] = sB2[t];
        __syncthreads();
    }
    if (t < 100) g_k2inv[bh * 100 + t] = sV[t];
}

// -------- fused k3 softmax (over S) @ V, all 10 landmarks per block --------
#define K3V_SMEM ((Mm * HDd + Mm * Ss + 4 * Mm * HDd) * 4)   // 92800 B
__global__ void __launch_bounds__(256) k_k3v2() {
    int bh = blockIdx.x;
    extern __shared__ float dyn[];
    float* sq   = dyn;                        // [10][64]
    float* lg   = dyn + Mm * HDd;             // [10][Ss] logits -> exp
    float* sout = dyn + Mm * HDd + Mm * Ss;   // [4][10][64]
    __shared__ float red[256];
    __shared__ float sinv[Mm];
    int t = threadIdx.x, lane = t & 31, w = t >> 5;
    for (int i = t; i < Mm * HDd; i += 256) sq[i] = g_Ql[bh * Mm * HDd + i];
    __syncthreads();
    for (int s = w; s < Ss; s += 8) {
        const float* Kr = g_K + ((size_t)bh * Ss + s) * 64;
        float ka = Kr[lane], kb = Kr[lane + 32];
#pragma unroll
        for (int m = 0; m < Mm; m++) {
            float p = ka * sq[m * 64 + lane] + kb * sq[m * 64 + lane + 32];
#pragma unroll
            for (int o = 16; o; o >>= 1) p += __shfl_xor_sync(0xffffffffu, p, o);
            if (lane == m) lg[m * Ss + s] = p;
        }
    }
    __syncthreads();
    for (int m = 0; m < Mm; m++) {
        float mx = -1e30f;
        for (int s = t; s < Ss; s += 256) mx = fmaxf(mx, lg[m * Ss + s]);
        red[t] = mx; __syncthreads();
        for (int o = 128; o; o >>= 1) { if (t < o) red[t] = fmaxf(red[t], red[t + o]); __syncthreads(); }
        mx = red[0]; __syncthreads();
        float sm = 0.f;
        for (int s = t; s < Ss; s += 256) { float e = expf(lg[m * Ss + s] - mx); lg[m * Ss + s] = e; sm += e; }
        red[t] = sm; __syncthreads();
        for (int o = 128; o; o >>= 1) { if (t < o) red[t] += red[t + o]; __syncthreads(); }
        if (t == 0) sinv[m] = 1.f / red[0];
        __syncthreads();
    }
    int d = t & 63, gg = t >> 6;
    float acc[Mm];
#pragma unroll
    for (int m = 0; m < Mm; m++) acc[m] = 0.f;
    for (int s = gg; s < Ss; s += 4) {
        float v = g_V[((size_t)bh * Ss + s) * 64 + d];
#pragma unroll
        for (int m = 0; m < Mm; m++) acc[m] += lg[m * Ss + s] * v;
    }
#pragma unroll
    for (int m = 0; m < Mm; m++) sout[(gg * Mm + m) * 64 + d] = acc[m];
    __syncthreads();
    for (int i = t; i < Mm * HDd; i += 256) {
        int m = i >> 6;
        float v = sout[i] + sout[Mm * 64 + i] + sout[2 * Mm * 64 + i] + sout[3 * Mm * 64 + i];
        g_k3V[bh * Mm * HDd + i] = v * sinv[m];
    }
}

// -------- coeff = softmax(Q @ Kl^T) @ inv(k2), per s -----------------------
__global__ void k_coeff() {
    int bh = blockIdx.x, t = threadIdx.x, lane = t & 31, w = t >> 5;
    __shared__ float sKl[Mm][64];
    __shared__ float sInv[100];
    for (int i = t; i < Mm * 64; i += 256) sKl[i / 64][i % 64] = g_Kl[bh * Mm * 64 + i];
    if (t < 100) sInv[t] = g_k2inv[bh * 100 + t];
    __syncthreads();
    for (int s = w; s < Ss; s += 8) {
        const float* Qr = g_Q + ((size_t)bh * Ss + s) * 64;
        float qa = Qr[lane], qb = Qr[lane + 32];
        float lg[10];
#pragma unroll
        for (int mm = 0; mm < 10; mm++) {
            float p = qa * sKl[mm][lane] + qb * sKl[mm][lane + 32];
#pragma unroll
            for (int o = 16; o; o >>= 1) p += __shfl_xor_sync(0xffffffffu, p, o);
            lg[mm] = p;
        }
        float mx = lg[0];
#pragma unroll
        for (int mm = 1; mm < 10; mm++) mx = fmaxf(mx, lg[mm]);
        float sum = 0.f;
#pragma unroll
        for (int mm = 0; mm < 10; mm++) { lg[mm] = expf(lg[mm] - mx); sum += lg[mm]; }
        float is = 1.f / sum;
        if (lane < 10) {
            float c = 0.f;
#pragma unroll
            for (int mm = 0; mm < 10; mm++) c += lg[mm] * sInv[mm * 10 + lane];
            g_coeff[((size_t)bh * Ss + s) * Mm + lane] = c * is;
        }
    }
}

// -------- attn[b,s,h*64+d] = coeff[s,:] @ k3V ------------------------------
__global__ void k_attn() {
    int bh = blockIdx.x;
    int s0 = blockIdx.y * 50;
    int b = bh / Hh, h = bh % Hh;
    __shared__ float sc[50][10];
    __shared__ float sw[10][64];
    int t = threadIdx.x;
    for (int i = t; i < 500; i += 256) sc[i / 10][i % 10] = g_coeff[((size_t)bh * Ss + s0) * Mm + i];
    for (int i = t; i < 640; i += 256) sw[i / 64][i % 64] = g_k3V[bh * Mm * 64 + i];
    __syncthreads();
    int d = t & 63, si0 = t >> 6;
    for (int si = si0; si < 50; si += 4) {
        float v = 0.f;
#pragma unroll
        for (int n = 0; n < 10; n++) v += sc[si][n] * sw[n][d];
        g_attn[((size_t)(b * Ss + s0 + si)) * Ee + h * 64 + d] = v;
    }
}

// -------- layernorm over last dim (E=1024), row per block ------------------
__global__ void k_ln(const float* __restrict__ x, const float* __restrict__ g,
                     const float* __restrict__ be, float* __restrict__ y) {
    int row = blockIdx.x, t = threadIdx.x;
    const float* xr = x + (size_t)row * Ee;
    __shared__ float r1[256], r2[256];
    float s = 0.f, ss = 0.f;
    for (int e = t; e < Ee; e += 256) { float v = xr[e]; s += v; ss += v * v; }
    r1[t] = s; r2[t] = ss; __syncthreads();
    for (int o = 128; o; o >>= 1) {
        if (t < o) { r1[t] += r1[t + o]; r2[t] += r2[t + o]; }
        __syncthreads();
    }
    float mu = r1[0] * (1.f / Ee);
    float var = r2[0] * (1.f / Ee) - mu * mu;
    float rstd = rsqrtf(var + LNEPS);
    for (int e = t; e < Ee; e += 256) {
        float v = xr[e];
        y[(size_t)row * Ee + e] = (v - mu) * rstd * g[e] + be[e];
    }
}

// ---------------------------------------------------------------------------
extern "C" void kernel_launch(void* const* d_in, const int* in_sizes, int n_in,
                              void* d_out, int out_size) {
    (void)in_sizes; (void)n_in; (void)out_size;
    const float* X   = (const float*)d_in[0];
    const float* Wq  = (const float*)d_in[1];
    const float* bq  = (const float*)d_in[2];
    const float* Wk  = (const float*)d_in[3];
    const float* bk  = (const float*)d_in[4];
    const float* Wv  = (const float*)d_in[5];
    const float* bv  = (const float*)d_in[6];
    const float* g1  = (const float*)d_in[7];
    const float* be1 = (const float*)d_in[8];
    const float* W1  = (const float*)d_in[9];
    const float* b1  = (const float*)d_in[10];
    const float* W2  = (const float*)d_in[11];
    const float* b2  = (const float*)d_in[12];
    const float* g2  = (const float*)d_in[13];
    const float* be2 = (const float*)d_in[14];
    float* out = (float*)d_out;

    float *pXT, *pQ, *pK, *pV, *pAttn, *pH1, *pMid, *pH2;
    cudaGetSymbolAddress((void**)&pXT,  g_XT);
    cudaGetSymbolAddress((void**)&pQ,   g_Q);
    cudaGetSymbolAddress((void**)&pK,   g_K);
    cudaGetSymbolAddress((void**)&pV,   g_V);
    cudaGetSymbolAddress((void**)&pAttn,g_attn);
    cudaGetSymbolAddress((void**)&pH1,  g_h1);
    cudaGetSymbolAddress((void**)&pMid, g_mid);
    cudaGetSymbolAddress((void**)&pH2,  g_h2);

    static int smem_set = 0;
    if (!smem_set) {
        cudaFuncSetAttribute(k_tgemm, cudaFuncAttributeMaxDynamicSharedMemorySize,
                             TGEMM_SMEM);
        cudaFuncSetAttribute(k_k3v2, cudaFuncAttributeMaxDynamicSharedMemorySize,
                             K3V_SMEM);
        smem_set = 1;
    }

    dim3 tb32(32, 8);
    // 1. X (B,E,S) -> XT (B,S,E)
    k_transpose_in<<<dim3((Ss + 31) / 32, Ee / 32, Bb), tb32>>>(X);
    // 2. QKV projections (fp16 tensor GEMM, M=16000, N=1024, K=1024)
    k_tgemm<<<dim3(125, 8), 512, TGEMM_SMEM>>>(pXT, Wq, bq, pQ, Ee, Hh * HDd, 0, QKSCALE);
    k_tgemm<<<dim3(125, 8), 512, TGEMM_SMEM>>>(pXT, Wk, bk, pK, Ee, Hh * HDd, 0, QKSCALE);
    k_tgemm<<<dim3(125, 8), 512, TGEMM_SMEM>>>(pXT, Wv, bv, pV, Ee, Hh * HDd, 0, 1.0f);
    // 3. landmarks
    k_landmarks<<<BH * Mm, 64>>>();
    // 4. k2 softmax
    k_k2<<<BH, 128>>>();
    // 5. global normalization scalar
    k_norm<<<1, 256>>>();
    // 6. 10x10 Newton inverse per (b,h)
    k_inv<<<BH, 128>>>();
    // 7. fused k3-softmax @ V (all landmarks per block; K,V read once)
    k_k3v2<<<BH, 256, K3V_SMEM>>>();
    // 8. coeff = softmax(Q Kl^T) @ inv
    k_coeff<<<BH, 256>>>();
    // 9. attn assembly -> (B,S,E)
    k_attn<<<dim3(BH, Ss / 50), 256>>>();
    // 10. LN1
    k_ln<<<Bb * Ss, 256>>>(pAttn, g1, be1, pH1);
    // 11. MLP1 + exact GELU (M=16000, N=4096, K=1024)
    k_tgemm<<<dim3(125, 32), 512, TGEMM_SMEM>>>(pH1, W1, b1, pMid, Ee, MLPn, 1, 1.0f);
    // 12. MLP2 (M=16000, N=1024, K=4096)
    k_tgemm<<<dim3(125, 8), 512, TGEMM_SMEM>>>(pMid, W2, b2, pH2, MLPn, Ee, 2, 1.0f);
    // 13. LN2 -> g_h1 (reuse)
    k_ln<<<Bb * Ss, 256>>>(pH2, g2, be2, pH1);
    // 14. (B,S,E) -> out (B,E,S)
    k_transpose_out<<<dim3(Ee / 32, (Ss + 31) / 32, Bb), tb32>>>(out);
}

// round 10
// speedup vs baseline: 3.2958x; 1.7526x over previous
#include <cuda_runtime.h>
#include <cuda_fp16.h>
#include <math.h>
#include <stdint.h>

// Problem dims (fixed)
#define Bb   8
#define Ee   1024
#define Ss   2000
#define Hh   16
#define HDd  64
#define Mm   10
#define MLPn 4096
#define SEG  200      // Ss / Mm
#define BH   128      // Bb * Hh
#define LNEPS 1e-5f
#define QKSCALE 0.35355339059327373f   // 64^-0.25

// ---------------- scratch (static device memory; no allocation allowed) ----
__device__ __half g_XTh [(size_t)Bb*Ss*Ee];     // (B,S,E) fp16
__device__ __half g_Wqh [Hh*HDd*Ee];
__device__ __half g_Wkh [Hh*HDd*Ee];
__device__ __half g_Wvh [Hh*HDd*Ee];
__device__ __half g_W1h [(size_t)MLPn*Ee];
__device__ __half g_W2h [(size_t)Ee*MLPn];
__device__ __half g_h1h [(size_t)Bb*Ss*Ee];     // LN1 out fp16 (MLP1 A)
__device__ __half g_midh[(size_t)Bb*Ss*MLPn];   // GELU out fp16 (MLP2 A)
__device__ float g_Q   [(size_t)BH*Ss*HDd];     // (B,H,S,HD) scaled
__device__ float g_K   [(size_t)BH*Ss*HDd];
__device__ float g_V   [(size_t)BH*Ss*HDd];
__device__ float g_Ql  [BH*Mm*HDd];
__device__ float g_Kl  [BH*Mm*HDd];
__device__ float g_k2  [BH*Mm*Mm];
__device__ float g_k2inv[BH*Mm*Mm];
__device__ float g_normv;
__device__ float g_k3V [BH*Mm*HDd];
__device__ float g_coeff[(size_t)BH*Ss*Mm];
__device__ float g_attn[(size_t)Bb*Ss*Ee];      // (B,S,E)
__device__ float g_h1  [(size_t)Bb*Ss*Ee];      // LN2 out f32
__device__ float g_h2  [(size_t)Bb*Ss*Ee];      // MLP2 out f32

// ====================== helpers ============================================
__device__ __forceinline__ uint32_t smem_u32(const void* p) {
    uint32_t a;
    asm("{ .reg .u64 t; cvta.to.shared.u64 t, %1; cvt.u32.u64 %0, t; }"
        : "=r"(a) : "l"(p));
    return a;
}
#define CP_ASYNC16(dst, src) \
    asm volatile("cp.async.cg.shared.global [%0], [%1], 16;" :: "r"(dst), "l"(src) : "memory")
#define CP_COMMIT() asm volatile("cp.async.commit_group;" ::: "memory")
#define CP_WAIT(n)  asm volatile("cp.async.wait_group %0;" :: "n"(n) : "memory")
#define LDSM_X4(r0, r1, r2, r3, addr) \
    asm volatile("ldmatrix.sync.aligned.m8n8.x4.shared.b16 {%0,%1,%2,%3}, [%4];" \
                 : "=r"(r0), "=r"(r1), "=r"(r2), "=r"(r3) : "r"(addr))

// -------- fp32 -> fp16 bulk convert (weights, once per launch) -------------
__global__ void k_w2h(const float* __restrict__ w, __half* __restrict__ o, int n4) {
    int i = blockIdx.x * 256 + threadIdx.x;
    if (i < n4) {
        float4 v = *(const float4*)(w + (size_t)i * 4);
        __half2 h0 = __floats2half2_rn(v.x, v.y);
        __half2 h1 = __floats2half2_rn(v.z, v.w);
        *(__half2*)(o + (size_t)i * 4)     = h0;
        *(__half2*)(o + (size_t)i * 4 + 2) = h1;
    }
}

// ---------------- transpose in: X (B,E,S) -> g_XTh (B,S,E) fp16 ------------
__global__ void k_transpose_in(const float* __restrict__ X) {
    __shared__ float t[32][33];
    int b = blockIdx.z;
    int s0 = blockIdx.x * 32, e0 = blockIdx.y * 32;
    int tx = threadIdx.x, ty = threadIdx.y;
#pragma unroll
    for (int i = 0; i < 4; i++) {
        int e = e0 + ty + i * 8, s = s0 + tx;
        if (s < Ss) t[ty + i * 8][tx] = X[((size_t)b * Ee + e) * Ss + s];
    }
    __syncthreads();
#pragma unroll
    for (int i = 0; i < 4; i++) {
        int s = s0 + ty + i * 8, e = e0 + tx;
        if (s < Ss) g_XTh[((size_t)b * Ss + s) * Ee + e] = __float2half_rn(t[tx][ty + i * 8]);
    }
}

// ---------------- transpose out: g_h1 (B,S,E) -> out (B,E,S) ---------------
__global__ void k_transpose_out(float* __restrict__ out) {
    __shared__ float t[32][33];
    int b = blockIdx.z;
    int e0 = blockIdx.x * 32, s0 = blockIdx.y * 32;
    int tx = threadIdx.x, ty = threadIdx.y;
#pragma unroll
    for (int i = 0; i < 4; i++) {
        int s = s0 + ty + i * 8, e = e0 + tx;
        if (s < Ss) t[ty + i * 8][tx] = g_h1[((size_t)b * Ss + s) * Ee + e];
    }
    __syncthreads();
#pragma unroll
    for (int i = 0; i < 4; i++) {
        int e = e0 + ty + i * 8, s = s0 + tx;
        if (s < Ss) out[((size_t)b * Ee + e) * Ss + s] = t[tx][ty + i * 8];
    }
}

// ============ fp16 cp.async + ldmatrix NT GEMM, fp32 accumulate ============
// C = A(MxK,f16) * W(NxK,f16)^T + bias(f32)
// BM=BN=128, BK=64, STAGES=4 (128 KB smem). 512 threads = 16 warps 4x4,
// warp tile 32x32 (2 mfrag x 4 nfrag m16n8k16).
// smem per stage: A[128][64] f16 (128B rows, 16B-chunk XOR swizzle), B same.
// mode 0: f32 scatter (B,H,S,HD) *scale | 1: GELU -> f16 | 2: plain f32
#define STAGES 4
#define STG_BYTES 32768
#define HGEMM_SMEM (STAGES * STG_BYTES)   // 131072

__global__ void __launch_bounds__(512) k_hgemm(
    const __half* __restrict__ A, const __half* __restrict__ W,
    const float* __restrict__ bias, void* __restrict__ Cv,
    int Kdim, int Ndim, int mode, float scale)
{
    extern __shared__ char smc[];
    const uint32_t smb = smem_u32(smc);
    const int tid = threadIdx.x;
    const int lane = tid & 31, warp = tid >> 5;
    const int warpRow = warp >> 2, warpCol = warp & 3;
    const int g = lane >> 2, t4c = lane & 3;
    const size_t row0 = (size_t)blockIdx.x * 128;
    const size_t col0 = (size_t)blockIdx.y * 128;

    // ---- loader geometry: 2 chunks of A + 2 of B per thread per tile ----
    int lrow[2], lch[2];
    uint32_t dsto[2];
    size_t srco[2];
#pragma unroll
    for (int i = 0; i < 2; i++) {
        int idx = tid + i * 512;          // 0..1023
        int row = idx >> 3, ch = idx & 7;
        lrow[i] = row; lch[i] = ch;
        dsto[i] = row * 128 + ((ch ^ (row & 7)) << 4);
        srco[i] = (size_t)row * Kdim + ch * 8;
    }

    // ---- ldmatrix addresses (stage-relative) ----
    const int j = lane >> 3, r8 = lane & 7;
    // A: matrix j -> rowhalf = j&1, kchalf = j>>1
    uint32_t aRow[2];
#pragma unroll
    for (int mf = 0; mf < 2; mf++)
        aRow[mf] = warpRow * 32 + mf * 16 + (j & 1) * 8 + r8;
    const int aKc = j >> 1;
    // B: matrix j -> nf = base + (j>>1), kchalf = j&1
    uint32_t bRow[2];
#pragma unroll
    for (int p = 0; p < 2; p++)
        bRow[p] = warpCol * 32 + (2 * p + (j >> 1)) * 8 + r8;
    const int bKc = j & 1;

    float acc[2][4][4];
#pragma unroll
    for (int mf = 0; mf < 2; mf++)
#pragma unroll
        for (int nf = 0; nf < 4; nf++)
#pragma unroll
            for (int q = 0; q < 4; q++) acc[mf][nf][q] = 0.f;

    const int KT = Kdim >> 6;   // BK=64

    // ---- prologue: issue STAGES-1 tile loads ----
#pragma unroll
    for (int pf = 0; pf < STAGES - 1; pf++) {
        if (pf < KT) {
            const __half* Ag = A + row0 * Kdim + (size_t)pf * 64;
            const __half* Wg = W + col0 * Kdim + (size_t)pf * 64;
            uint32_t sb = smb + pf * STG_BYTES;
#pragma unroll
            for (int i = 0; i < 2; i++) {
                CP_ASYNC16(sb + dsto[i], Ag + srco[i]);
                CP_ASYNC16(sb + 16384 + dsto[i], Wg + srco[i]);
            }
        }
        CP_COMMIT();
    }

    for (int kt = 0; kt < KT; kt++) {
        CP_WAIT(STAGES - 2);
        __syncthreads();
        // issue load for kt+STAGES-1 (its stage was last read in iter kt-1)
        {
            int nk = kt + STAGES - 1;
            if (nk < KT) {
                const __half* Ag = A + row0 * Kdim + (size_t)nk * 64;
                const __half* Wg = W + col0 * Kdim + (size_t)nk * 64;
                uint32_t sb = smb + (nk & (STAGES - 1)) * STG_BYTES;
#pragma unroll
                for (int i = 0; i < 2; i++) {
                    CP_ASYNC16(sb + dsto[i], Ag + srco[i]);
                    CP_ASYNC16(sb + 16384 + dsto[i], Wg + srco[i]);
                }
            }
            CP_COMMIT();
        }
        // compute on stage kt
        const uint32_t sA = smb + (kt & (STAGES - 1)) * STG_BYTES;
        const uint32_t sB = sA + 16384;
#pragma unroll
        for (int ks = 0; ks < 4; ks++) {
            uint32_t a[2][4], b[4][2];
#pragma unroll
            for (int mf = 0; mf < 2; mf++) {
                uint32_t kc = ks * 2 + aKc;
                uint32_t ad = sA + aRow[mf] * 128 + ((kc ^ (aRow[mf] & 7)) << 4);
                LDSM_X4(a[mf][0], a[mf][1], a[mf][2], a[mf][3], ad);
            }
#pragma unroll
            for (int p = 0; p < 2; p++) {
                uint32_t kc = ks * 2 + bKc;
                uint32_t bd = sB + bRow[p] * 128 + ((kc ^ (bRow[p] & 7)) << 4);
                uint32_t t0, t1, t2, t3;
                LDSM_X4(t0, t1, t2, t3, bd);
                b[2 * p][0] = t0; b[2 * p][1] = t1;
                b[2 * p + 1][0] = t2; b[2 * p + 1][1] = t3;
            }
#pragma unroll
            for (int mf = 0; mf < 2; mf++)
#pragma unroll
                for (int nf = 0; nf < 4; nf++) {
                    asm volatile(
                        "mma.sync.aligned.m16n8k16.row.col.f32.f16.f16.f32 "
                        "{%0,%1,%2,%3},{%4,%5,%6,%7},{%8,%9},{%0,%1,%2,%3};"
                        : "+f"(acc[mf][nf][0]), "+f"(acc[mf][nf][1]),
                          "+f"(acc[mf][nf][2]), "+f"(acc[mf][nf][3])
                        : "r"(a[mf][0]), "r"(a[mf][1]), "r"(a[mf][2]), "r"(a[mf][3]),
                          "r"(b[nf][0]), "r"(b[nf][1]));
                }
        }
        __syncthreads();
    }

    // ---- epilogue ----
#pragma unroll
    for (int mf = 0; mf < 2; mf++) {
#pragma unroll
        for (int h2 = 0; h2 < 2; h2++) {
            const size_t r = row0 + warpRow * 32 + mf * 16 + g + h2 * 8;
#pragma unroll
            for (int nf = 0; nf < 4; nf++) {
                const int c = (int)col0 + warpCol * 32 + nf * 8 + t4c * 2;
                float v0 = acc[mf][nf][h2 * 2 + 0] + bias[c];
                float v1 = acc[mf][nf][h2 * 2 + 1] + bias[c + 1];
                if (mode == 0) {
                    v0 *= scale; v1 *= scale;
                    int bb = (int)(r / Ss), s = (int)(r % Ss);
                    int h = c >> 6, d = c & 63;
                    *(float2*)&((float*)Cv)[(((size_t)(bb * Hh + h)) * Ss + s) * HDd + d]
                        = make_float2(v0, v1);
                } else if (mode == 1) {
                    v0 = 0.5f * v0 * (1.f + erff(v0 * 0.7071067811865475f));
                    v1 = 0.5f * v1 * (1.f + erff(v1 * 0.7071067811865475f));
                    *(__half2*)&((__half*)Cv)[r * Ndim + c] = __floats2half2_rn(v0, v1);
                } else {
                    *(float2*)&((float*)Cv)[r * Ndim + c] = make_float2(v0, v1);
                }
            }
        }
    }
}

// ---------------- landmarks: segment means over 200 s ----------------------
__global__ void k_landmarks() {
    int bhm = blockIdx.x;
    int m = bhm % Mm, bh = bhm / Mm;
    int d = threadIdx.x;  // 64
    const float* Qb = g_Q + ((size_t)bh * Ss + m * SEG) * HDd + d;
    const float* Kb = g_K + ((size_t)bh * Ss + m * SEG) * HDd + d;
    float aq = 0.f, ak = 0.f;
    for (int jj = 0; jj < SEG; jj++) { aq += Qb[(size_t)jj * HDd]; ak += Kb[(size_t)jj * HDd]; }
    g_Ql[(bh * Mm + m) * HDd + d] = aq * (1.f / SEG);
    g_Kl[(bh * Mm + m) * HDd + d] = ak * (1.f / SEG);
}

// ---------------- k2 = softmax(Ql @ Kl^T), per (b,h) -----------------------
__global__ void k_k2() {
    int bh = blockIdx.x;
    __shared__ float sQ[Mm * HDd], sK[Mm * HDd], sl[Mm][Mm];
    int t = threadIdx.x;  // 128
    for (int i = t; i < Mm * HDd; i += 128) {
        sQ[i] = g_Ql[bh * Mm * HDd + i];
        sK[i] = g_Kl[bh * Mm * HDd + i];
    }
    __syncthreads();
    if (t < 100) {
        int i = t / 10, jj = t % 10;
        float s = 0.f;
#pragma unroll
        for (int d = 0; d < 64; d++) s += sQ[i * 64 + d] * sK[jj * 64 + d];
        sl[i][jj] = s;
    }
    __syncthreads();
    if (t < 100) {
        int i = t / 10, jj = t % 10;
        float mx = -1e30f;
#pragma unroll
        for (int k = 0; k < 10; k++) mx = fmaxf(mx, sl[i][k]);
        float sum = 0.f;
#pragma unroll
        for (int k = 0; k < 10; k++) sum += expf(sl[i][k] - mx);
        g_k2[bh * 100 + t] = expf(sl[i][jj] - mx) / sum;
    }
}

// ------- global normalization: max colsum(|k2|) * max rowsum(|k2|) --------
__global__ void k_norm() {
    __shared__ float rc[256], rr[256];
    int t = threadIdx.x;
    float mc = 0.f, mr = 0.f;
    for (int idx = t; idx < BH * Mm; idx += 256) {
        int bh = idx / Mm, jj = idx % Mm;
        const float* Kp = g_k2 + bh * 100;
        float cs = 0.f, rs = 0.f;
#pragma unroll
        for (int i = 0; i < 10; i++) { cs += fabsf(Kp[i * 10 + jj]); rs += fabsf(Kp[jj * 10 + i]); }
        mc = fmaxf(mc, cs); mr = fmaxf(mr, rs);
    }
    rc[t] = mc; rr[t] = mr; __syncthreads();
    for (int o = 128; o > 0; o >>= 1) {
        if (t < o) { rc[t] = fmaxf(rc[t], rc[t + o]); rr[t] = fmaxf(rr[t], rr[t + o]); }
        __syncthreads();
    }
    if (t == 0) g_normv = rc[0] * rr[0];
}

// ---------------- Newton-Schulz iterative inverse of 10x10 k2 --------------
__global__ void k_inv() {
    int bh = blockIdx.x, t = threadIdx.x;  // 128 threads
    __shared__ float sK[100], sV[100], sKV[100], sA[100], sB2[100];
    if (t < 100) sK[t] = g_k2[bh * 100 + t];
    __syncthreads();
    float denom = g_normv;
    int i = t / 10, jj = t % 10;
    if (t < 100) sV[t] = sK[jj * 10 + i] / denom;
    __syncthreads();
    for (int it = 0; it < 6; it++) {
        if (t < 100) { float s = 0.f;
#pragma unroll
            for (int k = 0; k < 10; k++) s += sK[i * 10 + k] * sV[k * 10 + jj];
            sKV[t] = s; }
        __syncthreads();
        if (t < 100) sA[t] = (i == jj ? 7.f : 0.f) - sKV[t];
        __syncthreads();
        if (t < 100) { float s = 0.f;
#pragma unroll
            for (int k = 0; k < 10; k++) s += sKV[i * 10 + k] * sA[k * 10 + jj];
            sB2[t] = (i == jj ? 15.f : 0.f) - s; }
        __syncthreads();
        if (t < 100) { float s = 0.f;
#pragma unroll
            for (int k = 0; k < 10; k++) s += sKV[i * 10 + k] * sB2[k * 10 + jj];
            sA[t] = (i == jj ? 13.f : 0.f) - s; }
        __syncthreads();
        if (t < 100) { float s = 0.f;
#pragma unroll
            for (int k = 0; k < 10; k++) s += sV[i * 10 + k] * sA[k * 10 + jj];
            sB2[t] = 0.25f * s; }
        __syncthreads();
        if (t < 100) sV[t] = sB2[t];
        __syncthreads();
    }
    if (t < 100) g_k2inv[bh * 100 + t] = sV[t];
}

// -------- fused k3 softmax (over S) @ V, all 10 landmarks per block --------
#define K3V_SMEM ((Mm * HDd + Mm * Ss + 4 * Mm * HDd) * 4)   // 92800 B
__global__ void __launch_bounds__(256) k_k3v2() {
    int bh = blockIdx.x;
    extern __shared__ float dyn[];
    float* sq   = dyn;
    float* lg   = dyn + Mm * HDd;
    float* sout = dyn + Mm * HDd + Mm * Ss;
    __shared__ float red[256];
    __shared__ float sinv[Mm];
    int t = threadIdx.x, lane = t & 31, w = t >> 5;
    for (int i = t; i < Mm * HDd; i += 256) sq[i] = g_Ql[bh * Mm * HDd + i];
    __syncthreads();
    for (int s = w; s < Ss; s += 8) {
        const float* Kr = g_K + ((size_t)bh * Ss + s) * 64;
        float ka = Kr[lane], kb = Kr[lane + 32];
#pragma unroll
        for (int m = 0; m < Mm; m++) {
            float p = ka * sq[m * 64 + lane] + kb * sq[m * 64 + lane + 32];
#pragma unroll
            for (int o = 16; o; o >>= 1) p += __shfl_xor_sync(0xffffffffu, p, o);
            if (lane == m) lg[m * Ss + s] = p;
        }
    }
    __syncthreads();
    for (int m = 0; m < Mm; m++) {
        float mx = -1e30f;
        for (int s = t; s < Ss; s += 256) mx = fmaxf(mx, lg[m * Ss + s]);
        red[t] = mx; __syncthreads();
        for (int o = 128; o; o >>= 1) { if (t < o) red[t] = fmaxf(red[t], red[t + o]); __syncthreads(); }
        mx = red[0]; __syncthreads();
        float sm = 0.f;
        for (int s = t; s < Ss; s += 256) { float e = expf(lg[m * Ss + s] - mx); lg[m * Ss + s] = e; sm += e; }
        red[t] = sm; __syncthreads();
        for (int o = 128; o; o >>= 1) { if (t < o) red[t] += red[t + o]; __syncthreads(); }
        if (t == 0) sinv[m] = 1.f / red[0];
        __syncthreads();
    }
    int d = t & 63, gg = t >> 6;
    float acc[Mm];
#pragma unroll
    for (int m = 0; m < Mm; m++) acc[m] = 0.f;
    for (int s = gg; s < Ss; s += 4) {
        float v = g_V[((size_t)bh * Ss + s) * 64 + d];
#pragma unroll
        for (int m = 0; m < Mm; m++) acc[m] += lg[m * Ss + s] * v;
    }
#pragma unroll
    for (int m = 0; m < Mm; m++) sout[(gg * Mm + m) * 64 + d] = acc[m];
    __syncthreads();
    for (int i = t; i < Mm * HDd; i += 256) {
        int m = i >> 6;
        float v = sout[i] + sout[Mm * 64 + i] + sout[2 * Mm * 64 + i] + sout[3 * Mm * 64 + i];
        g_k3V[bh * Mm * HDd + i] = v * sinv[m];
    }
}

// -------- coeff = softmax(Q @ Kl^T) @ inv(k2), per s -----------------------
__global__ void k_coeff() {
    int bh = blockIdx.x, t = threadIdx.x, lane = t & 31, w = t >> 5;
    __shared__ float sKl[Mm][64];
    __shared__ float sInv[100];
    for (int i = t; i < Mm * 64; i += 256) sKl[i / 64][i % 64] = g_Kl[bh * Mm * 64 + i];
    if (t < 100) sInv[t] = g_k2inv[bh * 100 + t];
    __syncthreads();
    for (int s = w; s < Ss; s += 8) {
        const float* Qr = g_Q + ((size_t)bh * Ss + s) * 64;
        float qa = Qr[lane], qb = Qr[lane + 32];
        float lg[10];
#pragma unroll
        for (int mm = 0; mm < 10; mm++) {
            float p = qa * sKl[mm][lane] + qb * sKl[mm][lane + 32];
#pragma unroll
            for (int o = 16; o; o >>= 1) p += __shfl_xor_sync(0xffffffffu, p, o);
            lg[mm] = p;
        }
        float mx = lg[0];
#pragma unroll
        for (int mm = 1; mm < 10; mm++) mx = fmaxf(mx, lg[mm]);
        float sum = 0.f;
#pragma unroll
        for (int mm = 0; mm < 10; mm++) { lg[mm] = expf(lg[mm] - mx); sum += lg[mm]; }
        float is = 1.f / sum;
        if (lane < 10) {
            float c = 0.f;
#pragma unroll
            for (int mm = 0; mm < 10; mm++) c += lg[mm] * sInv[mm * 10 + lane];
            g_coeff[((size_t)bh * Ss + s) * Mm + lane] = c * is;
        }
    }
}

// -------- attn[b,s,h*64+d] = coeff[s,:] @ k3V ------------------------------
__global__ void k_attn() {
    int bh = blockIdx.x;
    int s0 = blockIdx.y * 50;
    int b = bh / Hh, h = bh % Hh;
    __shared__ float sc[50][10];
    __shared__ float sw[10][64];
    int t = threadIdx.x;
    for (int i = t; i < 500; i += 256) sc[i / 10][i % 10] = g_coeff[((size_t)bh * Ss + s0) * Mm + i];
    for (int i = t; i < 640; i += 256) sw[i / 64][i % 64] = g_k3V[bh * Mm * 64 + i];
    __syncthreads();
    int d = t & 63, si0 = t >> 6;
    for (int si = si0; si < 50; si += 4) {
        float v = 0.f;
#pragma unroll
        for (int n = 0; n < 10; n++) v += sc[si][n] * sw[n][d];
        g_attn[((size_t)(b * Ss + s0 + si)) * Ee + h * 64 + d] = v;
    }
}

// -------- layernorm over E=1024; writes f32 or f16 -------------------------
__global__ void k_ln(const float* __restrict__ x, const float* __restrict__ g,
                     const float* __restrict__ be, void* __restrict__ y, int half_out) {
    int row = blockIdx.x, t = threadIdx.x;
    const float* xr = x + (size_t)row * Ee;
    __shared__ float r1[256], r2[256];
    float s = 0.f, ss = 0.f;
    for (int e = t; e < Ee; e += 256) { float v = xr[e]; s += v; ss += v * v; }
    r1[t] = s; r2[t] = ss; __syncthreads();
    for (int o = 128; o; o >>= 1) {
        if (t < o) { r1[t] += r1[t + o]; r2[t] += r2[t + o]; }
        __syncthreads();
    }
    float mu = r1[0] * (1.f / Ee);
    float var = r2[0] * (1.f / Ee) - mu * mu;
    float rstd = rsqrtf(var + LNEPS);
    for (int e = t; e < Ee; e += 256) {
        float v = (xr[e] - mu) * rstd * g[e] + be[e];
        if (half_out) ((__half*)y)[(size_t)row * Ee + e] = __float2half_rn(v);
        else          ((float*)y)[(size_t)row * Ee + e] = v;
    }
}

// ---------------------------------------------------------------------------
extern "C" void kernel_launch(void* const* d_in, const int* in_sizes, int n_in,
                              void* d_out, int out_size) {
    (void)in_sizes; (void)n_in; (void)out_size;
    const float* X   = (const float*)d_in[0];
    const float* Wq  = (const float*)d_in[1];
    const float* bq  = (const float*)d_in[2];
    const float* Wk  = (const float*)d_in[3];
    const float* bk  = (const float*)d_in[4];
    const float* Wv  = (const float*)d_in[5];
    const float* bv  = (const float*)d_in[6];
    const float* g1  = (const float*)d_in[7];
    const float* be1 = (const float*)d_in[8];
    const float* W1  = (const float*)d_in[9];
    const float* b1  = (const float*)d_in[10];
    const float* W2  = (const float*)d_in[11];
    const float* b2  = (const float*)d_in[12];
    const float* g2  = (const float*)d_in[13];
    const float* be2 = (const float*)d_in[14];
    float* out = (float*)d_out;

    __half *pXTh, *pWqh, *pWkh, *pWvh, *pW1h, *pW2h, *pH1h, *pMidh;
    float *pQ, *pK, *pV, *pAttn, *pH1, *pH2;
    cudaGetSymbolAddress((void**)&pXTh,  g_XTh);
    cudaGetSymbolAddress((void**)&pWqh,  g_Wqh);
    cudaGetSymbolAddress((void**)&pWkh,  g_Wkh);
    cudaGetSymbolAddress((void**)&pWvh,  g_Wvh);
    cudaGetSymbolAddress((void**)&pW1h,  g_W1h);
    cudaGetSymbolAddress((void**)&pW2h,  g_W2h);
    cudaGetSymbolAddress((void**)&pH1h,  g_h1h);
    cudaGetSymbolAddress((void**)&pMidh, g_midh);
    cudaGetSymbolAddress((void**)&pQ,    g_Q);
    cudaGetSymbolAddress((void**)&pK,    g_K);
    cudaGetSymbolAddress((void**)&pV,    g_V);
    cudaGetSymbolAddress((void**)&pAttn, g_attn);
    cudaGetSymbolAddress((void**)&pH1,   g_h1);
    cudaGetSymbolAddress((void**)&pH2,   g_h2);

    static int smem_set = 0;
    if (!smem_set) {
        cudaFuncSetAttribute(k_hgemm, cudaFuncAttributeMaxDynamicSharedMemorySize,
                             HGEMM_SMEM);
        cudaFuncSetAttribute(k_k3v2, cudaFuncAttributeMaxDynamicSharedMemorySize,
                             K3V_SMEM);
        smem_set = 1;
    }

    dim3 tb32(32, 8);
    // 0. weight conversions (f32 -> f16), once per launch
    k_w2h<<<(Hh * HDd * Ee / 4 + 255) / 256, 256>>>(Wq, pWqh, Hh * HDd * Ee / 4);
    k_w2h<<<(Hh * HDd * Ee / 4 + 255) / 256, 256>>>(Wk, pWkh, Hh * HDd * Ee / 4);
    k_w2h<<<(Hh * HDd * Ee / 4 + 255) / 256, 256>>>(Wv, pWvh, Hh * HDd * Ee / 4);
    k_w2h<<<(MLPn * Ee / 4 + 255) / 256, 256>>>(W1, pW1h, MLPn * Ee / 4);
    k_w2h<<<(Ee * MLPn / 4 + 255) / 256, 256>>>(W2, pW2h, Ee * MLPn / 4);
    // 1. X (B,E,S) -> XTh (B,S,E) fp16
    k_transpose_in<<<dim3((Ss + 31) / 32, Ee / 32, Bb), tb32>>>(X);
    // 2. QKV projections
    k_hgemm<<<dim3(125, 8), 512, HGEMM_SMEM>>>(pXTh, pWqh, bq, pQ, Ee, Hh * HDd, 0, QKSCALE);
    k_hgemm<<<dim3(125, 8), 512, HGEMM_SMEM>>>(pXTh, pWkh, bk, pK, Ee, Hh * HDd, 0, QKSCALE);
    k_hgemm<<<dim3(125, 8), 512, HGEMM_SMEM>>>(pXTh, pWvh, bv, pV, Ee, Hh * HDd, 0, 1.0f);
    // 3-9. attention path (f32)
    k_landmarks<<<BH * Mm, 64>>>();
    k_k2<<<BH, 128>>>();
    k_norm<<<1, 256>>>();
    k_inv<<<BH, 128>>>();
    k_k3v2<<<BH, 256, K3V_SMEM>>>();
    k_coeff<<<BH, 256>>>();
    k_attn<<<dim3(BH, Ss / 50), 256>>>();
    // 10. LN1 -> fp16
    k_ln<<<Bb * Ss, 256>>>(pAttn, g1, be1, pH1h, 1);
    // 11. MLP1 + GELU -> fp16 mid
    k_hgemm<<<dim3(125, 32), 512, HGEMM_SMEM>>>(pH1h, pW1h, b1, pMidh, Ee, MLPn, 1, 1.0f);
    // 12. MLP2 -> f32 h2
    k_hgemm<<<dim3(125, 8), 512, HGEMM_SMEM>>>(pMidh, pW2h, b2, pH2, MLPn, Ee, 2, 1.0f);
    // 13. LN2 -> f32 h1
    k_ln<<<Bb * Ss, 256>>>(pH2, g2, be2, pH1, 0);
    // 14. (B,S,E) -> out (B,E,S)
    k_transpose_out<<<dim3(Ee / 32, (Ss + 31) / 32, Bb), tb32>>>(out);
}

// round 15
// speedup vs baseline: 3.7435x; 1.1358x over previous
#include <cuda_runtime.h>
#include <cuda_fp16.h>
#include <math.h>
#include <stdint.h>

// Problem dims (fixed)
#define Bb   8
#define Ee   1024
#define Ss   2000
#define Hh   16
#define HDd  64
#define Mm   10
#define MLPn 4096
#define SEG  200      // Ss / Mm
#define BH   128      // Bb * Hh
#define LNEPS 1e-5f
#define QKSCALE 0.35355339059327373f   // 64^-0.25
#define QKV_SLAB ((size_t)BH * Ss * HDd)   // 16,384,000

// ---------------- scratch (static device memory) ---------------------------
__device__ __half g_XTh  [(size_t)Bb*Ss*Ee];      // (B,S,E) fp16
__device__ __half g_Wqkvh[(size_t)3*1024*Ee];     // packed QKV weights fp16
__device__ float  g_bqkv [3 * 1024];              // packed QKV biases
__device__ __half g_W1h  [(size_t)MLPn*Ee];
__device__ __half g_W2h  [(size_t)Ee*MLPn];
__device__ __half g_h1h  [(size_t)Bb*Ss*Ee];      // LN1 out fp16 (MLP1 A)
__device__ __half g_midh [(size_t)Bb*Ss*MLPn];    // GELU out fp16 (MLP2 A)
__device__ float  g_QKV  [3 * QKV_SLAB];          // Q | K | V, (B,H,S,HD)
__device__ float  g_Ql   [BH*Mm*HDd];
__device__ float  g_Kl   [BH*Mm*HDd];
__device__ float  g_k2   [BH*Mm*Mm];
__device__ float  g_k2inv[BH*Mm*Mm];
__device__ float  g_normv;
__device__ float  g_k3V  [BH*Mm*HDd];
__device__ float  g_coeff[(size_t)BH*Ss*Mm];
__device__ float  g_attn [(size_t)Bb*Ss*Ee];      // (B,S,E)
__device__ float  g_h1   [(size_t)Bb*Ss*Ee];      // LN2 out f32
__device__ float  g_h2   [(size_t)Bb*Ss*Ee];      // MLP2 out f32

// ====================== helpers ============================================
__device__ __forceinline__ uint32_t smem_u32(const void* p) {
    uint32_t a;
    asm("{ .reg .u64 t; cvta.to.shared.u64 t, %1; cvt.u32.u64 %0, t; }"
        : "=r"(a) : "l"(p));
    return a;
}
#define CP_ASYNC16(dst, src) \
    asm volatile("cp.async.cg.shared.global [%0], [%1], 16;" :: "r"(dst), "l"(src) : "memory")
#define CP_COMMIT() asm volatile("cp.async.commit_group;" ::: "memory")
#define CP_WAIT(n)  asm volatile("cp.async.wait_group %0;" :: "n"(n) : "memory")
#define LDSM_X4(r0, r1, r2, r3, addr) \
    asm volatile("ldmatrix.sync.aligned.m8n8.x4.shared.b16 {%0,%1,%2,%3}, [%4];" \
                 : "=r"(r0), "=r"(r1), "=r"(r2), "=r"(r3) : "r"(addr))

// -------- fp32 -> fp16 bulk convert --------------------------------------
__global__ void k_w2h(const float* __restrict__ w, __half* __restrict__ o, int n4) {
    int i = blockIdx.x * 256 + threadIdx.x;
    if (i < n4) {
        float4 v = *(const float4*)(w + (size_t)i * 4);
        *(__half2*)(o + (size_t)i * 4)     = __floats2half2_rn(v.x, v.y);
        *(__half2*)(o + (size_t)i * 4 + 2) = __floats2half2_rn(v.z, v.w);
    }
}
__global__ void k_packb(const float* __restrict__ bq, const float* __restrict__ bk,
                        const float* __restrict__ bv, float* __restrict__ o) {
    int i = blockIdx.x * 256 + threadIdx.x;
    if (i < 1024) o[i] = bq[i];
    else if (i < 2048) o[i] = bk[i - 1024];
    else if (i < 3072) o[i] = bv[i - 2048];
}

// ---------------- transpose in: X (B,E,S) -> g_XTh (B,S,E) fp16 ------------
__global__ void k_transpose_in(const float* __restrict__ X) {
    __shared__ float t[32][33];
    int b = blockIdx.z;
    int s0 = blockIdx.x * 32, e0 = blockIdx.y * 32;
    int tx = threadIdx.x, ty = threadIdx.y;
#pragma unroll
    for (int i = 0; i < 4; i++) {
        int e = e0 + ty + i * 8, s = s0 + tx;
        if (s < Ss) t[ty + i * 8][tx] = X[((size_t)b * Ee + e) * Ss + s];
    }
    __syncthreads();
#pragma unroll
    for (int i = 0; i < 4; i++) {
        int s = s0 + ty + i * 8, e = e0 + tx;
        if (s < Ss) g_XTh[((size_t)b * Ss + s) * Ee + e] = __float2half_rn(t[tx][ty + i * 8]);
    }
}

// ---------------- transpose out: g_h1 (B,S,E) -> out (B,E,S) ---------------
__global__ void k_transpose_out(float* __restrict__ out) {
    __shared__ float t[32][33];
    int b = blockIdx.z;
    int e0 = blockIdx.x * 32, s0 = blockIdx.y * 32;
    int tx = threadIdx.x, ty = threadIdx.y;
#pragma unroll
    for (int i = 0; i < 4; i++) {
        int s = s0 + ty + i * 8, e = e0 + tx;
        if (s < Ss) t[ty + i * 8][tx] = g_h1[((size_t)b * Ss + s) * Ee + e];
    }
    __syncthreads();
#pragma unroll
    for (int i = 0; i < 4; i++) {
        int e = e0 + ty + i * 8, s = s0 + tx;
        if (s < Ss) out[((size_t)b * Ee + e) * Ss + s] = t[tx][ty + i * 8];
    }
}

// ============ fp16 cp.async + ldmatrix NT GEMM, fp32 accumulate ============
// mode 0: QKV scatter (c<2048 scaled) | 1: GELU -> f16 | 2: plain f32
#define STAGES 4
#define STG_BYTES 32768
#define HGEMM_SMEM (STAGES * STG_BYTES)   // 131072

__global__ void __launch_bounds__(512) k_hgemm(
    const __half* __restrict__ A, const __half* __restrict__ W,
    const float* __restrict__ bias, void* __restrict__ Cv,
    int Kdim, int Ndim, int mode, float scale)
{
    extern __shared__ char smc[];
    const uint32_t smb = smem_u32(smc);
    const int tid = threadIdx.x;
    const int lane = tid & 31, warp = tid >> 5;
    const int warpRow = warp >> 2, warpCol = warp & 3;
    const int g = lane >> 2, t4c = lane & 3;
    const size_t row0 = (size_t)blockIdx.x * 128;
    const size_t col0 = (size_t)blockIdx.y * 128;

    uint32_t dsto[2];
    size_t srco[2];
#pragma unroll
    for (int i = 0; i < 2; i++) {
        int idx = tid + i * 512;
        int row = idx >> 3, ch = idx & 7;
        dsto[i] = row * 128 + ((ch ^ (row & 7)) << 4);
        srco[i] = (size_t)row * Kdim + ch * 8;
    }

    const int j = lane >> 3, r8 = lane & 7;
    uint32_t aRow[2];
#pragma unroll
    for (int mf = 0; mf < 2; mf++)
        aRow[mf] = warpRow * 32 + mf * 16 + (j & 1) * 8 + r8;
    const int aKc = j >> 1;
    uint32_t bRow[2];
#pragma unroll
    for (int p = 0; p < 2; p++)
        bRow[p] = warpCol * 32 + (2 * p + (j >> 1)) * 8 + r8;
    const int bKc = j & 1;

    float acc[2][4][4];
#pragma unroll
    for (int mf = 0; mf < 2; mf++)
#pragma unroll
        for (int nf = 0; nf < 4; nf++)
#pragma unroll
            for (int q = 0; q < 4; q++) acc[mf][nf][q] = 0.f;

    const int KT = Kdim >> 6;

#pragma unroll
    for (int pf = 0; pf < STAGES - 1; pf++) {
        if (pf < KT) {
            const __half* Ag = A + row0 * Kdim + (size_t)pf * 64;
            const __half* Wg = W + col0 * Kdim + (size_t)pf * 64;
            uint32_t sb = smb + pf * STG_BYTES;
#pragma unroll
            for (int i = 0; i < 2; i++) {
                CP_ASYNC16(sb + dsto[i], Ag + srco[i]);
                CP_ASYNC16(sb + 16384 + dsto[i], Wg + srco[i]);
            }
        }
        CP_COMMIT();
    }

    for (int kt = 0; kt < KT; kt++) {
        CP_WAIT(STAGES - 2);
        __syncthreads();
        {
            int nk = kt + STAGES - 1;
            if (nk < KT) {
                const __half* Ag = A + row0 * Kdim + (size_t)nk * 64;
                const __half* Wg = W + col0 * Kdim + (size_t)nk * 64;
                uint32_t sb = smb + (nk & (STAGES - 1)) * STG_BYTES;
#pragma unroll
                for (int i = 0; i < 2; i++) {
                    CP_ASYNC16(sb + dsto[i], Ag + srco[i]);
                    CP_ASYNC16(sb + 16384 + dsto[i], Wg + srco[i]);
                }
            }
            CP_COMMIT();
        }
        const uint32_t sA = smb + (kt & (STAGES - 1)) * STG_BYTES;
        const uint32_t sB = sA + 16384;
#pragma unroll
        for (int ks = 0; ks < 4; ks++) {
            uint32_t a[2][4], b[4][2];
#pragma unroll
            for (int mf = 0; mf < 2; mf++) {
                uint32_t kc = ks * 2 + aKc;
                uint32_t ad = sA + aRow[mf] * 128 + ((kc ^ (aRow[mf] & 7)) << 4);
                LDSM_X4(a[mf][0], a[mf][1], a[mf][2], a[mf][3], ad);
            }
#pragma unroll
            for (int p = 0; p < 2; p++) {
                uint32_t kc = ks * 2 + bKc;
                uint32_t bd = sB + bRow[p] * 128 + ((kc ^ (bRow[p] & 7)) << 4);
                uint32_t t0, t1, t2, t3;
                LDSM_X4(t0, t1, t2, t3, bd);
                b[2 * p][0] = t0; b[2 * p][1] = t1;
                b[2 * p + 1][0] = t2; b[2 * p + 1][1] = t3;
            }
#pragma unroll
            for (int mf = 0; mf < 2; mf++)
#pragma unroll
                for (int nf = 0; nf < 4; nf++) {
                    asm volatile(
                        "mma.sync.aligned.m16n8k16.row.col.f32.f16.f16.f32 "
                        "{%0,%1,%2,%3},{%4,%5,%6,%7},{%8,%9},{%0,%1,%2,%3};"
                        : "+f"(acc[mf][nf][0]), "+f"(acc[mf][nf][1]),
                          "+f"(acc[mf][nf][2]), "+f"(acc[mf][nf][3])
                        : "r"(a[mf][0]), "r"(a[mf][1]), "r"(a[mf][2]), "r"(a[mf][3]),
                          "r"(b[nf][0]), "r"(b[nf][1]));
                }
        }
        __syncthreads();
    }

#pragma unroll
    for (int mf = 0; mf < 2; mf++) {
#pragma unroll
        for (int h2 = 0; h2 < 2; h2++) {
            const size_t r = row0 + warpRow * 32 + mf * 16 + g + h2 * 8;
#pragma unroll
            for (int nf = 0; nf < 4; nf++) {
                const int c = (int)col0 + warpCol * 32 + nf * 8 + t4c * 2;
                float v0 = acc[mf][nf][h2 * 2 + 0] + bias[c];
                float v1 = acc[mf][nf][h2 * 2 + 1] + bias[c + 1];
                if (mode == 0) {
                    int s3 = c >> 10;              // 0=Q 1=K 2=V
                    float sc = (s3 < 2) ? scale : 1.0f;
                    v0 *= sc; v1 *= sc;
                    int bb = (int)(r / Ss), s = (int)(r % Ss);
                    int h = (c & 1023) >> 6, d = c & 63;
                    *(float2*)&((float*)Cv)[(size_t)s3 * QKV_SLAB
                        + (((size_t)(bb * Hh + h)) * Ss + s) * HDd + d]
                        = make_float2(v0, v1);
                } else if (mode == 1) {
                    v0 = 0.5f * v0 * (1.f + erff(v0 * 0.7071067811865475f));
                    v1 = 0.5f * v1 * (1.f + erff(v1 * 0.7071067811865475f));
                    *(__half2*)&((__half*)Cv)[r * Ndim + c] = __floats2half2_rn(v0, v1);
                } else {
                    *(float2*)&((float*)Cv)[r * Ndim + c] = make_float2(v0, v1);
                }
            }
        }
    }
}

// ---------------- landmarks: segment means over 200 s ----------------------
__global__ void k_landmarks() {
    int bhm = blockIdx.x;
    int m = bhm % Mm, bh = bhm / Mm;
    int d = threadIdx.x;  // 64
    const float* Qb = g_QKV + ((size_t)bh * Ss + m * SEG) * HDd + d;
    const float* Kb = g_QKV + QKV_SLAB + ((size_t)bh * Ss + m * SEG) * HDd + d;
    float aq = 0.f, ak = 0.f;
    for (int jj = 0; jj < SEG; jj++) { aq += Qb[(size_t)jj * HDd]; ak += Kb[(size_t)jj * HDd]; }
    g_Ql[(bh * Mm + m) * HDd + d] = aq * (1.f / SEG);
    g_Kl[(bh * Mm + m) * HDd + d] = ak * (1.f / SEG);
}

// ---------------- k2 = softmax(Ql @ Kl^T), per (b,h) -----------------------
__global__ void k_k2() {
    int bh = blockIdx.x;
    __shared__ float sQ[Mm * HDd], sK[Mm * HDd], sl[Mm][Mm];
    int t = threadIdx.x;  // 128
    for (int i = t; i < Mm * HDd; i += 128) {
        sQ[i] = g_Ql[bh * Mm * HDd + i];
        sK[i] = g_Kl[bh * Mm * HDd + i];
    }
    __syncthreads();
    if (t < 100) {
        int i = t / 10, jj = t % 10;
        float s = 0.f;
#pragma unroll
        for (int d = 0; d < 64; d++) s += sQ[i * 64 + d] * sK[jj * 64 + d];
        sl[i][jj] = s;
    }
    __syncthreads();
    if (t < 100) {
        int i = t / 10, jj = t % 10;
        float mx = -1e30f;
#pragma unroll
        for (int k = 0; k < 10; k++) mx = fmaxf(mx, sl[i][k]);
        float sum = 0.f;
#pragma unroll
        for (int k = 0; k < 10; k++) sum += expf(sl[i][k] - mx);
        g_k2[bh * 100 + t] = expf(sl[i][jj] - mx) / sum;
    }
}

// ------- global normalization --------------------------------------------
__global__ void k_norm() {
    __shared__ float rc[256], rr[256];
    int t = threadIdx.x;
    float mc = 0.f, mr = 0.f;
    for (int idx = t; idx < BH * Mm; idx += 256) {
        int bh = idx / Mm, jj = idx % Mm;
        const float* Kp = g_k2 + bh * 100;
        float cs = 0.f, rs = 0.f;
#pragma unroll
        for (int i = 0; i < 10; i++) { cs += fabsf(Kp[i * 10 + jj]); rs += fabsf(Kp[jj * 10 + i]); }
        mc = fmaxf(mc, cs); mr = fmaxf(mr, rs);
    }
    rc[t] = mc; rr[t] = mr; __syncthreads();
    for (int o = 128; o > 0; o >>= 1) {
        if (t < o) { rc[t] = fmaxf(rc[t], rc[t + o]); rr[t] = fmaxf(rr[t], rr[t + o]); }
        __syncthreads();
    }
    if (t == 0) g_normv = rc[0] * rr[0];
}

// ---------------- Newton-Schulz inverse of 10x10 k2 ------------------------
__global__ void k_inv() {
    int bh = blockIdx.x, t = threadIdx.x;
    __shared__ float sK[100], sV[100], sKV[100], sA[100], sB2[100];
    if (t < 100) sK[t] = g_k2[bh * 100 + t];
    __syncthreads();
    float denom = g_normv;
    int i = t / 10, jj = t % 10;
    if (t < 100) sV[t] = sK[jj * 10 + i] / denom;
    __syncthreads();
    for (int it = 0; it < 6; it++) {
        if (t < 100) { float s = 0.f;
#pragma unroll
            for (int k = 0; k < 10; k++) s += sK[i * 10 + k] * sV[k * 10 + jj];
            sKV[t] = s; }
        __syncthreads();
        if (t < 100) sA[t] = (i == jj ? 7.f : 0.f) - sKV[t];
        __syncthreads();
        if (t < 100) { float s = 0.f;
#pragma unroll
            for (int k = 0; k < 10; k++) s += sKV[i * 10 + k] * sA[k * 10 + jj];
            sB2[t] = (i == jj ? 15.f : 0.f) - s; }
        __syncthreads();
        if (t < 100) { float s = 0.f;
#pragma unroll
            for (int k = 0; k < 10; k++) s += sKV[i * 10 + k] * sB2[k * 10 + jj];
            sA[t] = (i == jj ? 13.f : 0.f) - s; }
        __syncthreads();
        if (t < 100) { float s = 0.f;
#pragma unroll
            for (int k = 0; k < 10; k++) s += sV[i * 10 + k] * sA[k * 10 + jj];
            sB2[t] = 0.25f * s; }
        __syncthreads();
        if (t < 100) sV[t] = sB2[t];
        __syncthreads();
    }
    if (t < 100) g_k2inv[bh * 100 + t] = sV[t];
}

// -------- fused k3 softmax (over S) @ V, all 10 landmarks per block --------
// logits via smem-tiled per-thread dots (no shuffles). K,V each read once.
#define K3V_SMEM ((Mm * HDd + Mm * Ss + 256 * 65) * 4)   // 149120 B
__global__ void __launch_bounds__(256) k_k3v2() {
    int bh = blockIdx.x;
    extern __shared__ float dyn[];
    float* sq  = dyn;                         // [10][64]
    float* lg  = dyn + Mm * HDd;              // [10][Ss]
    float* kb  = dyn + Mm * HDd + Mm * Ss;    // [256][65] K-rows / sout reuse
    __shared__ float red[256];
    __shared__ float sinv[Mm];
    int t = threadIdx.x;
    for (int i = t; i < Mm * HDd; i += 256) sq[i] = g_Ql[bh * Mm * HDd + i];
    __syncthreads();
    // ---- logits: tile 256 K-rows into smem, each thread dots its row x 10 --
    const float* Kg = g_QKV + QKV_SLAB + (size_t)bh * Ss * 64;
    for (int s0 = 0; s0 < Ss; s0 += 256) {
        int nrow = min(256, Ss - s0);
        for (int idx = t; idx < nrow * 64; idx += 256) {
            int r = idx >> 6, d = idx & 63;
            kb[r * 65 + d] = Kg[(size_t)(s0 + r) * 64 + d];
        }
        __syncthreads();
        if (t < nrow) {
#pragma unroll
            for (int m = 0; m < Mm; m++) {
                float acc = 0.f;
#pragma unroll
                for (int d = 0; d < 64; d++) acc += kb[t * 65 + d] * sq[m * 64 + d];
                lg[m * Ss + s0 + t] = acc;
            }
        }
        __syncthreads();
    }
    // ---- softmax over S per landmark ----
    for (int m = 0; m < Mm; m++) {
        float mx = -1e30f;
        for (int s = t; s < Ss; s += 256) mx = fmaxf(mx, lg[m * Ss + s]);
        red[t] = mx; __syncthreads();
        for (int o = 128; o; o >>= 1) { if (t < o) red[t] = fmaxf(red[t], red[t + o]); __syncthreads(); }
        mx = red[0]; __syncthreads();
        float sm = 0.f;
        for (int s = t; s < Ss; s += 256) { float e = expf(lg[m * Ss + s] - mx); lg[m * Ss + s] = e; sm += e; }
        red[t] = sm; __syncthreads();
        for (int o = 128; o; o >>= 1) { if (t < o) red[t] += red[t + o]; __syncthreads(); }
        if (t == 0) sinv[m] = 1.f / red[0];
        __syncthreads();
    }
    // ---- V pass: V read once, accumulate all 10 outputs ----
    float* sout = kb;   // reuse
    int d = t & 63, gg = t >> 6;
    float acc[Mm];
#pragma unroll
    for (int m = 0; m < Mm; m++) acc[m] = 0.f;
    const float* Vg = g_QKV + 2 * QKV_SLAB + (size_t)bh * Ss * 64;
    for (int s = gg; s < Ss; s += 4) {
        float v = Vg[(size_t)s * 64 + d];
#pragma unroll
        for (int m = 0; m < Mm; m++) acc[m] += lg[m * Ss + s] * v;
    }
#pragma unroll
    for (int m = 0; m < Mm; m++) sout[(gg * Mm + m) * 64 + d] = acc[m];
    __syncthreads();
    for (int i = t; i < Mm * HDd; i += 256) {
        int m = i >> 6;
        float v = sout[i] + sout[Mm * 64 + i] + sout[2 * Mm * 64 + i] + sout[3 * Mm * 64 + i];
        g_k3V[bh * Mm * HDd + i] = v * sinv[m];
    }
}

// -------- coeff = softmax(Q @ Kl^T) @ inv(k2): smem-tiled, no shuffles -----
#define COEFF_SMEM (256 * 65 * 4)   // 66560 B
__global__ void __launch_bounds__(256) k_coeff2() {
    int bh = blockIdx.x, t = threadIdx.x;
    extern __shared__ float sq[];   // [256][65]
    __shared__ float sKl[Mm * HDd];
    __shared__ float sInv[100];
    for (int i = t; i < Mm * HDd; i += 256) sKl[i] = g_Kl[bh * Mm * HDd + i];
    if (t < 100) sInv[t] = g_k2inv[bh * 100 + t];
    __syncthreads();
    const float* Qg = g_QKV + (size_t)bh * Ss * 64;
    for (int s0 = 0; s0 < Ss; s0 += 256) {
        int nrow = min(256, Ss - s0);
        for (int idx = t; idx < nrow * 64; idx += 256) {
            int r = idx >> 6, d = idx & 63;
            sq[r * 65 + d] = Qg[(size_t)(s0 + r) * 64 + d];
        }
        __syncthreads();
        if (t < nrow) {
            float lg[Mm];
#pragma unroll
            for (int m = 0; m < Mm; m++) {
                float acc = 0.f;
#pragma unroll
                for (int d = 0; d < 64; d++) acc += sq[t * 65 + d] * sKl[m * 64 + d];
                lg[m] = acc;
            }
            float mx = lg[0];
#pragma unroll
            for (int m = 1; m < Mm; m++) mx = fmaxf(mx, lg[m]);
            float sum = 0.f;
#pragma unroll
            for (int m = 0; m < Mm; m++) { lg[m] = expf(lg[m] - mx); sum += lg[m]; }
            float is = 1.f / sum;
            float* cp = &g_coeff[((size_t)bh * Ss + s0 + t) * Mm];
#pragma unroll
            for (int n = 0; n < Mm; n++) {
                float c = 0.f;
#pragma unroll
                for (int m = 0; m < Mm; m++) c += lg[m] * sInv[m * 10 + n];
                cp[n] = c * is;
            }
        }
        __syncthreads();
    }
}

// -------- attn[b,s,h*64+d] = coeff[s,:] @ k3V ------------------------------
__global__ void k_attn() {
    int bh = blockIdx.x;
    int s0 = blockIdx.y * 50;
    int b = bh / Hh, h = bh % Hh;
    __shared__ float sc[50][10];
    __shared__ float sw[10][64];
    int t = threadIdx.x;
    for (int i = t; i < 500; i += 256) sc[i / 10][i % 10] = g_coeff[((size_t)bh * Ss + s0) * Mm + i];
    for (int i = t; i < 640; i += 256) sw[i / 64][i % 64] = g_k3V[bh * Mm * 64 + i];
    __syncthreads();
    int d = t & 63, si0 = t >> 6;
    for (int si = si0; si < 50; si += 4) {
        float v = 0.f;
#pragma unroll
        for (int n = 0; n < 10; n++) v += sc[si][n] * sw[n][d];
        g_attn[((size_t)(b * Ss + s0 + si)) * Ee + h * 64 + d] = v;
    }
}

// -------- layernorm over E=1024; writes f32 or f16 -------------------------
__global__ void k_ln(const float* __restrict__ x, const float* __restrict__ g,
                     const float* __restrict__ be, void* __restrict__ y, int half_out) {
    int row = blockIdx.x, t = threadIdx.x;
    const float* xr = x + (size_t)row * Ee;
    __shared__ float r1[256], r2[256];
    float s = 0.f, ss = 0.f;
    for (int e = t; e < Ee; e += 256) { float v = xr[e]; s += v; ss += v * v; }
    r1[t] = s; r2[t] = ss; __syncthreads();
    for (int o = 128; o; o >>= 1) {
        if (t < o) { r1[t] += r1[t + o]; r2[t] += r2[t + o]; }
        __syncthreads();
    }
    float mu = r1[0] * (1.f / Ee);
    float var = r2[0] * (1.f / Ee) - mu * mu;
    float rstd = rsqrtf(var + LNEPS);
    for (int e = t; e < Ee; e += 256) {
        float v = (xr[e] - mu) * rstd * g[e] + be[e];
        if (half_out) ((__half*)y)[(size_t)row * Ee + e] = __float2half_rn(v);
        else          ((float*)y)[(size_t)row * Ee + e] = v;
    }
}

// ---------------------------------------------------------------------------
extern "C" void kernel_launch(void* const* d_in, const int* in_sizes, int n_in,
                              void* d_out, int out_size) {
    (void)in_sizes; (void)n_in; (void)out_size;
    const float* X   = (const float*)d_in[0];
    const float* Wq  = (const float*)d_in[1];
    const float* bq  = (const float*)d_in[2];
    const float* Wk  = (const float*)d_in[3];
    const float* bk  = (const float*)d_in[4];
    const float* Wv  = (const float*)d_in[5];
    const float* bv  = (const float*)d_in[6];
    const float* g1  = (const float*)d_in[7];
    const float* be1 = (const float*)d_in[8];
    const float* W1  = (const float*)d_in[9];
    const float* b1  = (const float*)d_in[10];
    const float* W2  = (const float*)d_in[11];
    const float* b2  = (const float*)d_in[12];
    const float* g2  = (const float*)d_in[13];
    const float* be2 = (const float*)d_in[14];
    float* out = (float*)d_out;

    __half *pXTh, *pWqkvh, *pW1h, *pW2h, *pH1h, *pMidh;
    float *pQKV, *pBqkv, *pAttn, *pH1, *pH2;
    cudaGetSymbolAddress((void**)&pXTh,   g_XTh);
    cudaGetSymbolAddress((void**)&pWqkvh, g_Wqkvh);
    cudaGetSymbolAddress((void**)&pBqkv,  g_bqkv);
    cudaGetSymbolAddress((void**)&pW1h,   g_W1h);
    cudaGetSymbolAddress((void**)&pW2h,   g_W2h);
    cudaGetSymbolAddress((void**)&pH1h,   g_h1h);
    cudaGetSymbolAddress((void**)&pMidh,  g_midh);
    cudaGetSymbolAddress((void**)&pQKV,   g_QKV);
    cudaGetSymbolAddress((void**)&pAttn,  g_attn);
    cudaGetSymbolAddress((void**)&pH1,    g_h1);
    cudaGetSymbolAddress((void**)&pH2,    g_h2);

    static int smem_set = 0;
    if (!smem_set) {
        cudaFuncSetAttribute(k_hgemm, cudaFuncAttributeMaxDynamicSharedMemorySize,
                             HGEMM_SMEM);
        cudaFuncSetAttribute(k_k3v2, cudaFuncAttributeMaxDynamicSharedMemorySize,
                             K3V_SMEM);
        cudaFuncSetAttribute(k_coeff2, cudaFuncAttributeMaxDynamicSharedMemorySize,
                             COEFF_SMEM);
        smem_set = 1;
    }

    const int NW = 1024 * Ee / 4;   // elements/4 per QKV weight
    dim3 tb32(32, 8);
    // 0. pack weights (f32 -> f16) + biases
    k_w2h<<<(NW + 255) / 256, 256>>>(Wq, pWqkvh, NW);
    k_w2h<<<(NW + 255) / 256, 256>>>(Wk, pWqkvh + (size_t)1024 * Ee, NW);
    k_w2h<<<(NW + 255) / 256, 256>>>(Wv, pWqkvh + (size_t)2048 * Ee, NW);
    k_w2h<<<(MLPn * Ee / 4 + 255) / 256, 256>>>(W1, pW1h, MLPn * Ee / 4);
    k_w2h<<<(Ee * MLPn / 4 + 255) / 256, 256>>>(W2, pW2h, Ee * MLPn / 4);
    k_packb<<<12, 256>>>(bq, bk, bv, pBqkv);
    // 1. X (B,E,S) -> XTh (B,S,E) fp16
    k_transpose_in<<<dim3((Ss + 31) / 32, Ee / 32, Bb), tb32>>>(X);
    // 2. fused QKV projection (N=3072)
    k_hgemm<<<dim3(125, 24), 512, HGEMM_SMEM>>>(pXTh, pWqkvh, pBqkv, pQKV,
                                                Ee, 3072, 0, QKSCALE);
    // 3-9. attention path
    k_landmarks<<<BH * Mm, 64>>>();
    k_k2<<<BH, 128>>>();
    k_norm<<<1, 256>>>();
    k_inv<<<BH, 128>>>();
    k_k3v2<<<BH, 256, K3V_SMEM>>>();
    k_coeff2<<<BH, 256, COEFF_SMEM>>>();
    k_attn<<<dim3(BH, Ss / 50), 256>>>();
    // 10. LN1 -> fp16
    k_ln<<<Bb * Ss, 256>>>(pAttn, g1, be1, pH1h, 1);
    // 11. MLP1 + GELU -> fp16 mid
    k_hgemm<<<dim3(125, 32), 512, HGEMM_SMEM>>>(pH1h, pW1h, b1, pMidh, Ee, MLPn, 1, 1.0f);
    // 12. MLP2 -> f32 h2
    k_hgemm<<<dim3(125, 8), 512, HGEMM_SMEM>>>(pMidh, pW2h, b2, pH2, MLPn, Ee, 2, 1.0f);
    // 13. LN2 -> f32 h1
    k_ln<<<Bb * Ss, 256>>>(pH2, g2, be2, pH1, 0);
    // 14. (B,S,E) -> out (B,E,S)
    k_transpose_out<<<dim3(Ee / 32, (Ss + 31) / 32, Bb), tb32>>>(out);
}

// round 17
// speedup vs baseline: 3.8446x; 1.0270x over previous
#include <cuda_runtime.h>
#include <cuda_fp16.h>
#include <math.h>
#include <stdint.h>

// Problem dims (fixed)
#define Bb   8
#define Ee   1024
#define Ss   2000
#define Hh   16
#define HDd  64
#define Mm   10
#define MLPn 4096
#define SEG  200      // Ss / Mm
#define BH   128      // Bb * Hh
#define LNEPS 1e-5f
#define QKSCALE 0.35355339059327373f   // 64^-0.25
#define QKV_SLAB ((size_t)BH * Ss * HDd)   // 16,384,000

// ---------------- scratch (static device memory) ---------------------------
__device__ __half g_XTh  [(size_t)Bb*Ss*Ee];      // (B,S,E) fp16
__device__ __half g_Wqkvh[(size_t)3*1024*Ee];     // packed QKV weights fp16
__device__ float  g_bqkv [3 * 1024];              // packed QKV biases
__device__ __half g_W1h  [(size_t)MLPn*Ee];
__device__ __half g_W2h  [(size_t)Ee*MLPn];
__device__ __half g_h1h  [(size_t)Bb*Ss*Ee];      // LN1 out fp16 (MLP1 A)
__device__ __half g_midh [(size_t)Bb*Ss*MLPn];    // GELU out fp16 (MLP2 A)
__device__ float  g_QKV  [3 * QKV_SLAB];          // Q | K | V, (B,H,S,HD)
__device__ float  g_Ql   [BH*Mm*HDd];
__device__ float  g_Kl   [BH*Mm*HDd];
__device__ float  g_k2   [BH*Mm*Mm];
__device__ float  g_k2inv[BH*Mm*Mm];
__device__ float  g_normv;
__device__ float  g_k3V  [BH*Mm*HDd];
__device__ float  g_coeff[(size_t)BH*Ss*Mm];
__device__ float  g_h2   [(size_t)Bb*Ss*Ee];      // MLP2 out f32
__device__ float  g_mu   [Bb*Ss];                 // LN2 row stats
__device__ float  g_rs   [Bb*Ss];

// ====================== helpers ============================================
__device__ __forceinline__ uint32_t smem_u32(const void* p) {
    uint32_t a;
    asm("{ .reg .u64 t; cvta.to.shared.u64 t, %1; cvt.u32.u64 %0, t; }"
        : "=r"(a) : "l"(p));
    return a;
}
#define CP_ASYNC16(dst, src) \
    asm volatile("cp.async.cg.shared.global [%0], [%1], 16;" :: "r"(dst), "l"(src) : "memory")
#define CP_COMMIT() asm volatile("cp.async.commit_group;" ::: "memory")
#define CP_WAIT(n)  asm volatile("cp.async.wait_group %0;" :: "n"(n) : "memory")
#define LDSM_X4(r0, r1, r2, r3, addr) \
    asm volatile("ldmatrix.sync.aligned.m8n8.x4.shared.b16 {%0,%1,%2,%3}, [%4];" \
                 : "=r"(r0), "=r"(r1), "=r"(r2), "=r"(r3) : "r"(addr))

// -------- all weight conversions in ONE launch -----------------------------
#define NQ4 (1024 * Ee / 4)          // 262144 float4 per QKV weight
#define NM4 ((int)((size_t)MLPn * Ee / 4))   // 1048576 per MLP weight
__global__ void k_w2hall(const float* __restrict__ Wq, const float* __restrict__ Wk,
                         const float* __restrict__ Wv, const float* __restrict__ W1,
                         const float* __restrict__ W2,
                         __half* __restrict__ oqkv, __half* __restrict__ o1,
                         __half* __restrict__ o2) {
    int i = blockIdx.x * 256 + threadIdx.x;
    const float* src; __half* dst; size_t off;
    if (i < NQ4)                { src = Wq; dst = oqkv;                       off = i; }
    else if (i < 2 * NQ4)       { src = Wk; dst = oqkv + (size_t)1024 * Ee;   off = i - NQ4; }
    else if (i < 3 * NQ4)       { src = Wv; dst = oqkv + (size_t)2048 * Ee;   off = i - 2 * NQ4; }
    else if (i < 3 * NQ4 + NM4) { src = W1; dst = o1;                         off = i - 3 * NQ4; }
    else if (i < 3 * NQ4 + 2 * NM4) { src = W2; dst = o2;                     off = i - 3 * NQ4 - NM4; }
    else return;
    float4 v = *(const float4*)(src + off * 4);
    *(__half2*)(dst + off * 4)     = __floats2half2_rn(v.x, v.y);
    *(__half2*)(dst + off * 4 + 2) = __floats2half2_rn(v.z, v.w);
}
__global__ void k_packb(const float* __restrict__ bq, const float* __restrict__ bk,
                        const float* __restrict__ bv, float* __restrict__ o) {
    int i = blockIdx.x * 256 + threadIdx.x;
    if (i < 1024) o[i] = bq[i];
    else if (i < 2048) o[i] = bk[i - 1024];
    else if (i < 3072) o[i] = bv[i - 2048];
}

// ---------------- transpose in: X (B,E,S) -> g_XTh (B,S,E) fp16 ------------
__global__ void k_transpose_in(const float* __restrict__ X) {
    __shared__ float t[32][33];
    int b = blockIdx.z;
    int s0 = blockIdx.x * 32, e0 = blockIdx.y * 32;
    int tx = threadIdx.x, ty = threadIdx.y;
#pragma unroll
    for (int i = 0; i < 4; i++) {
        int e = e0 + ty + i * 8, s = s0 + tx;
        if (s < Ss) t[ty + i * 8][tx] = X[((size_t)b * Ee + e) * Ss + s];
    }
    __syncthreads();
#pragma unroll
    for (int i = 0; i < 4; i++) {
        int s = s0 + ty + i * 8, e = e0 + tx;
        if (s < Ss) g_XTh[((size_t)b * Ss + s) * Ee + e] = __float2half_rn(t[tx][ty + i * 8]);
    }
}

// --------- fused transpose + LN2 apply: g_h2 (B,S,E) -> out (B,E,S) --------
__global__ void k_transpose_out_ln(float* __restrict__ out,
                                   const float* __restrict__ g2,
                                   const float* __restrict__ be2) {
    __shared__ float t[32][33];
    int b = blockIdx.z;
    int e0 = blockIdx.x * 32, s0 = blockIdx.y * 32;
    int tx = threadIdx.x, ty = threadIdx.y;
#pragma unroll
    for (int i = 0; i < 4; i++) {
        int s = s0 + ty + i * 8, e = e0 + tx;
        if (s < Ss) t[ty + i * 8][tx] = g_h2[((size_t)b * Ss + s) * Ee + e];
    }
    __syncthreads();
    int s = s0 + tx;
    float mu = 0.f, rs = 0.f;
    if (s < Ss) { mu = g_mu[b * Ss + s]; rs = g_rs[b * Ss + s]; }
#pragma unroll
    for (int i = 0; i < 4; i++) {
        int e = e0 + ty + i * 8;
        if (s < Ss)
            out[((size_t)b * Ee + e) * Ss + s] =
                (t[tx][ty + i * 8] - mu) * rs * g2[e] + be2[e];
    }
}

// ============ fp16 cp.async + ldmatrix NT GEMM, fp32 accumulate ============
// mode 0: QKV scatter (c<2048 scaled) | 1: GELU -> f16 | 2: plain f32
#define STAGES 4
#define STG_BYTES 32768
#define HGEMM_SMEM (STAGES * STG_BYTES)   // 131072

__global__ void __launch_bounds__(512) k_hgemm(
    const __half* __restrict__ A, const __half* __restrict__ W,
    const float* __restrict__ bias, void* __restrict__ Cv,
    int Kdim, int Ndim, int mode, float scale)
{
    extern __shared__ char smc[];
    const uint32_t smb = smem_u32(smc);
    const int tid = threadIdx.x;
    const int lane = tid & 31, warp = tid >> 5;
    const int warpRow = warp >> 2, warpCol = warp & 3;
    const int g = lane >> 2, t4c = lane & 3;
    const size_t row0 = (size_t)blockIdx.x * 128;
    const size_t col0 = (size_t)blockIdx.y * 128;

    uint32_t dsto[2];
    size_t srco[2];
#pragma unroll
    for (int i = 0; i < 2; i++) {
        int idx = tid + i * 512;
        int row = idx >> 3, ch = idx & 7;
        dsto[i] = row * 128 + ((ch ^ (row & 7)) << 4);
        srco[i] = (size_t)row * Kdim + ch * 8;
    }

    const int j = lane >> 3, r8 = lane & 7;
    uint32_t aRow[2];
#pragma unroll
    for (int mf = 0; mf < 2; mf++)
        aRow[mf] = warpRow * 32 + mf * 16 + (j & 1) * 8 + r8;
    const int aKc = j >> 1;
    uint32_t bRow[2];
#pragma unroll
    for (int p = 0; p < 2; p++)
        bRow[p] = warpCol * 32 + (2 * p + (j >> 1)) * 8 + r8;
    const int bKc = j & 1;

    float acc[2][4][4];
#pragma unroll
    for (int mf = 0; mf < 2; mf++)
#pragma unroll
        for (int nf = 0; nf < 4; nf++)
#pragma unroll
            for (int q = 0; q < 4; q++) acc[mf][nf][q] = 0.f;

    const int KT = Kdim >> 6;

#pragma unroll
    for (int pf = 0; pf < STAGES - 1; pf++) {
        if (pf < KT) {
            const __half* Ag = A + row0 * Kdim + (size_t)pf * 64;
            const __half* Wg = W + col0 * Kdim + (size_t)pf * 64;
            uint32_t sb = smb + pf * STG_BYTES;
#pragma unroll
            for (int i = 0; i < 2; i++) {
                CP_ASYNC16(sb + dsto[i], Ag + srco[i]);
                CP_ASYNC16(sb + 16384 + dsto[i], Wg + srco[i]);
            }
        }
        CP_COMMIT();
    }

    for (int kt = 0; kt < KT; kt++) {
        CP_WAIT(STAGES - 2);
        __syncthreads();
        {
            int nk = kt + STAGES - 1;
            if (nk < KT) {
                const __half* Ag = A + row0 * Kdim + (size_t)nk * 64;
                const __half* Wg = W + col0 * Kdim + (size_t)nk * 64;
                uint32_t sb = smb + (nk & (STAGES - 1)) * STG_BYTES;
#pragma unroll
                for (int i = 0; i < 2; i++) {
                    CP_ASYNC16(sb + dsto[i], Ag + srco[i]);
                    CP_ASYNC16(sb + 16384 + dsto[i], Wg + srco[i]);
                }
            }
            CP_COMMIT();
        }
        const uint32_t sA = smb + (kt & (STAGES - 1)) * STG_BYTES;
        const uint32_t sB = sA + 16384;
#pragma unroll
        for (int ks = 0; ks < 4; ks++) {
            uint32_t a[2][4], b[4][2];
#pragma unroll
            for (int mf = 0; mf < 2; mf++) {
                uint32_t kc = ks * 2 + aKc;
                uint32_t ad = sA + aRow[mf] * 128 + ((kc ^ (aRow[mf] & 7)) << 4);
                LDSM_X4(a[mf][0], a[mf][1], a[mf][2], a[mf][3], ad);
            }
#pragma unroll
            for (int p = 0; p < 2; p++) {
                uint32_t kc = ks * 2 + bKc;
                uint32_t bd = sB + bRow[p] * 128 + ((kc ^ (bRow[p] & 7)) << 4);
                uint32_t t0, t1, t2, t3;
                LDSM_X4(t0, t1, t2, t3, bd);
                b[2 * p][0] = t0; b[2 * p][1] = t1;
                b[2 * p + 1][0] = t2; b[2 * p + 1][1] = t3;
            }
#pragma unroll
            for (int mf = 0; mf < 2; mf++)
#pragma unroll
                for (int nf = 0; nf < 4; nf++) {
                    asm volatile(
                        "mma.sync.aligned.m16n8k16.row.col.f32.f16.f16.f32 "
                        "{%0,%1,%2,%3},{%4,%5,%6,%7},{%8,%9},{%0,%1,%2,%3};"
                        : "+f"(acc[mf][nf][0]), "+f"(acc[mf][nf][1]),
                          "+f"(acc[mf][nf][2]), "+f"(acc[mf][nf][3])
                        : "r"(a[mf][0]), "r"(a[mf][1]), "r"(a[mf][2]), "r"(a[mf][3]),
                          "r"(b[nf][0]), "r"(b[nf][1]));
                }
        }
        __syncthreads();
    }

#pragma unroll
    for (int mf = 0; mf < 2; mf++) {
#pragma unroll
        for (int h2 = 0; h2 < 2; h2++) {
            const size_t r = row0 + warpRow * 32 + mf * 16 + g + h2 * 8;
#pragma unroll
            for (int nf = 0; nf < 4; nf++) {
                const int c = (int)col0 + warpCol * 32 + nf * 8 + t4c * 2;
                float v0 = acc[mf][nf][h2 * 2 + 0] + bias[c];
                float v1 = acc[mf][nf][h2 * 2 + 1] + bias[c + 1];
                if (mode == 0) {
                    int s3 = c >> 10;              // 0=Q 1=K 2=V
                    float sc = (s3 < 2) ? scale : 1.0f;
                    v0 *= sc; v1 *= sc;
                    int bb = (int)(r / Ss), s = (int)(r % Ss);
                    int h = (c & 1023) >> 6, d = c & 63;
                    *(float2*)&((float*)Cv)[(size_t)s3 * QKV_SLAB
                        + (((size_t)(bb * Hh + h)) * Ss + s) * HDd + d]
                        = make_float2(v0, v1);
                } else if (mode == 1) {
                    v0 = 0.5f * v0 * (1.f + erff(v0 * 0.7071067811865475f));
                    v1 = 0.5f * v1 * (1.f + erff(v1 * 0.7071067811865475f));
                    *(__half2*)&((__half*)Cv)[r * Ndim + c] = __floats2half2_rn(v0, v1);
                } else {
                    *(float2*)&((float*)Cv)[r * Ndim + c] = make_float2(v0, v1);
                }
            }
        }
    }
}

// ---------------- landmarks: segment means over 200 s ----------------------
__global__ void k_landmarks() {
    int bhm = blockIdx.x;
    int m = bhm % Mm, bh = bhm / Mm;
    int d = threadIdx.x;  // 64
    const float* Qb = g_QKV + ((size_t)bh * Ss + m * SEG) * HDd + d;
    const float* Kb = g_QKV + QKV_SLAB + ((size_t)bh * Ss + m * SEG) * HDd + d;
    float aq = 0.f, ak = 0.f;
    for (int jj = 0; jj < SEG; jj++) { aq += Qb[(size_t)jj * HDd]; ak += Kb[(size_t)jj * HDd]; }
    g_Ql[(bh * Mm + m) * HDd + d] = aq * (1.f / SEG);
    g_Kl[(bh * Mm + m) * HDd + d] = ak * (1.f / SEG);
}

// ---------------- k2 = softmax(Ql @ Kl^T), per (b,h) -----------------------
__global__ void k_k2() {
    int bh = blockIdx.x;
    __shared__ float sQ[Mm * HDd], sK[Mm * HDd], sl[Mm][Mm];
    int t = threadIdx.x;  // 128
    for (int i = t; i < Mm * HDd; i += 128) {
        sQ[i] = g_Ql[bh * Mm * HDd + i];
        sK[i] = g_Kl[bh * Mm * HDd + i];
    }
    __syncthreads();
    if (t < 100) {
        int i = t / 10, jj = t % 10;
        float s = 0.f;
#pragma unroll
        for (int d = 0; d < 64; d++) s += sQ[i * 64 + d] * sK[jj * 64 + d];
        sl[i][jj] = s;
    }
    __syncthreads();
    if (t < 100) {
        int i = t / 10, jj = t % 10;
        float mx = -1e30f;
#pragma unroll
        for (int k = 0; k < 10; k++) mx = fmaxf(mx, sl[i][k]);
        float sum = 0.f;
#pragma unroll
        for (int k = 0; k < 10; k++) sum += expf(sl[i][k] - mx);
        g_k2[bh * 100 + t] = expf(sl[i][jj] - mx) / sum;
    }
}

// ------- global normalization --------------------------------------------
__global__ void k_norm() {
    __shared__ float rc[256], rr[256];
    int t = threadIdx.x;
    float mc = 0.f, mr = 0.f;
    for (int idx = t; idx < BH * Mm; idx += 256) {
        int bh = idx / Mm, jj = idx % Mm;
        const float* Kp = g_k2 + bh * 100;
        float cs = 0.f, rs = 0.f;
#pragma unroll
        for (int i = 0; i < 10; i++) { cs += fabsf(Kp[i * 10 + jj]); rs += fabsf(Kp[jj * 10 + i]); }
        mc = fmaxf(mc, cs); mr = fmaxf(mr, rs);
    }
    rc[t] = mc; rr[t] = mr; __syncthreads();
    for (int o = 128; o > 0; o >>= 1) {
        if (t < o) { rc[t] = fmaxf(rc[t], rc[t + o]); rr[t] = fmaxf(rr[t], rr[t + o]); }
        __syncthreads();
    }
    if (t == 0) g_normv = rc[0] * rr[0];
}

// ---------------- Newton-Schulz inverse of 10x10 k2 ------------------------
__global__ void k_inv() {
    int bh = blockIdx.x, t = threadIdx.x;
    __shared__ float sK[100], sV[100], sKV[100], sA[100], sB2[100];
    if (t < 100) sK[t] = g_k2[bh * 100 + t];
    __syncthreads();
    float denom = g_normv;
    int i = t / 10, jj = t % 10;
    if (t < 100) sV[t] = sK[jj * 10 + i] / denom;
    __syncthreads();
    for (int it = 0; it < 6; it++) {
        if (t < 100) { float s = 0.f;
#pragma unroll
            for (int k = 0; k < 10; k++) s += sK[i * 10 + k] * sV[k * 10 + jj];
            sKV[t] = s; }
        __syncthreads();
        if (t < 100) sA[t] = (i == jj ? 7.f : 0.f) - sKV[t];
        __syncthreads();
        if (t < 100) { float s = 0.f;
#pragma unroll
            for (int k = 0; k < 10; k++) s += sKV[i * 10 + k] * sA[k * 10 + jj];
            sB2[t] = (i == jj ? 15.f : 0.f) - s; }
        __syncthreads();
        if (t < 100) { float s = 0.f;
#pragma unroll
            for (int k = 0; k < 10; k++) s += sKV[i * 10 + k] * sB2[k * 10 + jj];
            sA[t] = (i == jj ? 13.f : 0.f) - s; }
        __syncthreads();
        if (t < 100) { float s = 0.f;
#pragma unroll
            for (int k = 0; k < 10; k++) s += sV[i * 10 + k] * sA[k * 10 + jj];
            sB2[t] = 0.25f * s; }
        __syncthreads();
        if (t < 100) sV[t] = sB2[t];
        __syncthreads();
    }
    if (t < 100) g_k2inv[bh * 100 + t] = sV[t];
}

// -------- fused k3 softmax (over S) @ V, all 10 landmarks per block --------
#define K3V_SMEM ((Mm * HDd + Mm * Ss + 256 * 65) * 4)   // 149120 B
__global__ void __launch_bounds__(256) k_k3v2() {
    int bh = blockIdx.x;
    extern __shared__ float dyn[];
    float* sq  = dyn;
    float* lg  = dyn + Mm * HDd;
    float* kb  = dyn + Mm * HDd + Mm * Ss;
    __shared__ float red[256];
    __shared__ float sinv[Mm];
    int t = threadIdx.x;
    for (int i = t; i < Mm * HDd; i += 256) sq[i] = g_Ql[bh * Mm * HDd + i];
    __syncthreads();
    const float* Kg = g_QKV + QKV_SLAB + (size_t)bh * Ss * 64;
    for (int s0 = 0; s0 < Ss; s0 += 256) {
        int nrow = min(256, Ss - s0);
        for (int idx = t; idx < nrow * 64; idx += 256) {
            int r = idx >> 6, d = idx & 63;
            kb[r * 65 + d] = Kg[(size_t)(s0 + r) * 64 + d];
        }
        __syncthreads();
        if (t < nrow) {
#pragma unroll
            for (int m = 0; m < Mm; m++) {
                float acc = 0.f;
#pragma unroll
                for (int d = 0; d < 64; d++) acc += kb[t * 65 + d] * sq[m * 64 + d];
                lg[m * Ss + s0 + t] = acc;
            }
        }
        __syncthreads();
    }
    for (int m = 0; m < Mm; m++) {
        float mx = -1e30f;
        for (int s = t; s < Ss; s += 256) mx = fmaxf(mx, lg[m * Ss + s]);
        red[t] = mx; __syncthreads();
        for (int o = 128; o; o >>= 1) { if (t < o) red[t] = fmaxf(red[t], red[t + o]); __syncthreads(); }
        mx = red[0]; __syncthreads();
        float sm = 0.f;
        for (int s = t; s < Ss; s += 256) { float e = expf(lg[m * Ss + s] - mx); lg[m * Ss + s] = e; sm += e; }
        red[t] = sm; __syncthreads();
        for (int o = 128; o; o >>= 1) { if (t < o) red[t] += red[t + o]; __syncthreads(); }
        if (t == 0) sinv[m] = 1.f / red[0];
        __syncthreads();
    }
    float* sout = kb;
    int d = t & 63, gg = t >> 6;
    float acc[Mm];
#pragma unroll
    for (int m = 0; m < Mm; m++) acc[m] = 0.f;
    const float* Vg = g_QKV + 2 * QKV_SLAB + (size_t)bh * Ss * 64;
    for (int s = gg; s < Ss; s += 4) {
        float v = Vg[(size_t)s * 64 + d];
#pragma unroll
        for (int m = 0; m < Mm; m++) acc[m] += lg[m * Ss + s] * v;
    }
#pragma unroll
    for (int m = 0; m < Mm; m++) sout[(gg * Mm + m) * 64 + d] = acc[m];
    __syncthreads();
    for (int i = t; i < Mm * HDd; i += 256) {
        int m = i >> 6;
        float v = sout[i] + sout[Mm * 64 + i] + sout[2 * Mm * 64 + i] + sout[3 * Mm * 64 + i];
        g_k3V[bh * Mm * HDd + i] = v * sinv[m];
    }
}

// -------- coeff = softmax(Q @ Kl^T) @ inv(k2): smem-tiled ------------------
#define COEFF_SMEM (256 * 65 * 4)   // 66560 B
__global__ void __launch_bounds__(256) k_coeff2() {
    int bh = blockIdx.x, t = threadIdx.x;
    extern __shared__ float sq[];   // [256][65]
    __shared__ float sKl[Mm * HDd];
    __shared__ float sInv[100];
    for (int i = t; i < Mm * HDd; i += 256) sKl[i] = g_Kl[bh * Mm * HDd + i];
    if (t < 100) sInv[t] = g_k2inv[bh * 100 + t];
    __syncthreads();
    const float* Qg = g_QKV + (size_t)bh * Ss * 64;
    for (int s0 = 0; s0 < Ss; s0 += 256) {
        int nrow = min(256, Ss - s0);
        for (int idx = t; idx < nrow * 64; idx += 256) {
            int r = idx >> 6, d = idx & 63;
            sq[r * 65 + d] = Qg[(size_t)(s0 + r) * 64 + d];
        }
        __syncthreads();
        if (t < nrow) {
            float lg[Mm];
#pragma unroll
            for (int m = 0; m < Mm; m++) {
                float acc = 0.f;
#pragma unroll
                for (int d = 0; d < 64; d++) acc += sq[t * 65 + d] * sKl[m * 64 + d];
                lg[m] = acc;
            }
            float mx = lg[0];
#pragma unroll
            for (int m = 1; m < Mm; m++) mx = fmaxf(mx, lg[m]);
            float sum = 0.f;
#pragma unroll
            for (int m = 0; m < Mm; m++) { lg[m] = expf(lg[m] - mx); sum += lg[m]; }
            float is = 1.f / sum;
            float* cp = &g_coeff[((size_t)bh * Ss + s0 + t) * Mm];
#pragma unroll
            for (int n = 0; n < Mm; n++) {
                float c = 0.f;
#pragma unroll
                for (int m = 0; m < Mm; m++) c += lg[m] * sInv[m * 10 + n];
                cp[n] = c * is;
            }
        }
        __syncthreads();
    }
}

// ====== fused attn assembly + LN1 -> h1h fp16 (no g_attn round-trip) ======
// block: (chunk of 40 s-rows, batch b). smem: k3V[16][10][64] + coeff[40][160]
// + g1/be1 preload. Each thread computes 4 e's per row (e = t + 256*i).
#define ATTNLN_SMEM ((16 * Mm * HDd + 40 * 160 + 2 * Ee) * 4)   // 74752 B
__global__ void __launch_bounds__(256) k_attn_ln(const float* __restrict__ g1,
                                                 const float* __restrict__ be1) {
    int b = blockIdx.y, s0 = blockIdx.x * 40;
    extern __shared__ float dyn[];
    float* sk  = dyn;                          // [16*10*64]
    float* sc  = dyn + 16 * Mm * HDd;          // [40][160]
    float* sg  = dyn + 16 * Mm * HDd + 40 * 160;       // [1024]
    float* sbe = sg + Ee;                              // [1024]
    __shared__ float wsum[8], wsq[8];
    __shared__ float sMu, sRs;
    int t = threadIdx.x, lane = t & 31, w = t >> 5;
    for (int i = t; i < 16 * Mm * HDd; i += 256) sk[i] = g_k3V[(size_t)b * 16 * Mm * HDd + i];
    for (int i = t; i < 16 * 400; i += 256) {
        int h = i / 400, rem = i % 400, s = rem / 10, m = rem % 10;
        sc[s * 160 + h * 10 + m] = g_coeff[((size_t)(b * 16 + h) * Ss + s0 + s) * Mm + m];
    }
    for (int i = t; i < Ee; i += 256) { sg[i] = g1[i]; sbe[i] = be1[i]; }
    __syncthreads();
    for (int r = 0; r < 40; r++) {
        const float* cr = sc + r * 160;
        float v[4], ps = 0.f, pq = 0.f;
#pragma unroll
        for (int i = 0; i < 4; i++) {
            int e = t + 256 * i, h = e >> 6, d = e & 63;
            float acc = 0.f;
#pragma unroll
            for (int m = 0; m < Mm; m++) acc += cr[h * 10 + m] * sk[(h * Mm + m) * 64 + d];
            v[i] = acc; ps += acc; pq += acc * acc;
        }
#pragma unroll
        for (int o = 16; o; o >>= 1) {
            ps += __shfl_xor_sync(0xffffffffu, ps, o);
            pq += __shfl_xor_sync(0xffffffffu, pq, o);
        }
        if (lane == 0) { wsum[w] = ps; wsq[w] = pq; }
        __syncthreads();
        if (t == 0) {
            float S = 0.f, Q2 = 0.f;
#pragma unroll
            for (int i = 0; i < 8; i++) { S += wsum[i]; Q2 += wsq[i]; }
            float mu = S * (1.f / Ee);
            sMu = mu; sRs = rsqrtf(Q2 * (1.f / Ee) - mu * mu + LNEPS);
        }
        __syncthreads();
        float mu = sMu, rs = sRs;
        __half* dst = g_h1h + ((size_t)b * Ss + s0 + r) * Ee;
#pragma unroll
        for (int i = 0; i < 4; i++) {
            int e = t + 256 * i;
            dst[e] = __float2half_rn((v[i] - mu) * rs * sg[e] + sbe[e]);
        }
    }
}

// -------- LN2 row stats (mu, rstd) over g_h2 -------------------------------
__global__ void k_lnstats() {
    int row = blockIdx.x, t = threadIdx.x;
    const float* xr = g_h2 + (size_t)row * Ee;
    __shared__ float r1[256], r2[256];
    float s = 0.f, ss = 0.f;
    for (int e = t; e < Ee; e += 256) { float v = xr[e]; s += v; ss += v * v; }
    r1[t] = s; r2[t] = ss; __syncthreads();
    for (int o = 128; o; o >>= 1) {
        if (t < o) { r1[t] += r1[t + o]; r2[t] += r2[t + o]; }
        __syncthreads();
    }
    if (t == 0) {
        float mu = r1[0] * (1.f / Ee);
        g_mu[row] = mu;
        g_rs[row] = rsqrtf(r2[0] * (1.f / Ee) - mu * mu + LNEPS);
    }
}

// ---------------------------------------------------------------------------
extern "C" void kernel_launch(void* const* d_in, const int* in_sizes, int n_in,
                              void* d_out, int out_size) {
    (void)in_sizes; (void)n_in; (void)out_size;
    const float* X   = (const float*)d_in[0];
    const float* Wq  = (const float*)d_in[1];
    const float* bq  = (const float*)d_in[2];
    const float* Wk  = (const float*)d_in[3];
    const float* bk  = (const float*)d_in[4];
    const float* Wv  = (const float*)d_in[5];
    const float* bv  = (const float*)d_in[6];
    const float* g1  = (const float*)d_in[7];
    const float* be1 = (const float*)d_in[8];
    const float* W1  = (const float*)d_in[9];
    const float* b1  = (const float*)d_in[10];
    const float* W2  = (const float*)d_in[11];
    const float* b2  = (const float*)d_in[12];
    const float* g2  = (const float*)d_in[13];
    const float* be2 = (const float*)d_in[14];
    float* out = (float*)d_out;

    __half *pXTh, *pWqkvh, *pW1h, *pW2h, *pH1h, *pMidh;
    float *pQKV, *pBqkv, *pH2;
    cudaGetSymbolAddress((void**)&pXTh,   g_XTh);
    cudaGetSymbolAddress((void**)&pWqkvh, g_Wqkvh);
    cudaGetSymbolAddress((void**)&pBqkv,  g_bqkv);
    cudaGetSymbolAddress((void**)&pW1h,   g_W1h);
    cudaGetSymbolAddress((void**)&pW2h,   g_W2h);
    cudaGetSymbolAddress((void**)&pH1h,   g_h1h);
    cudaGetSymbolAddress((void**)&pMidh,  g_midh);
    cudaGetSymbolAddress((void**)&pQKV,   g_QKV);
    cudaGetSymbolAddress((void**)&pH2,    g_h2);

    static int smem_set = 0;
    if (!smem_set) {
        cudaFuncSetAttribute(k_hgemm, cudaFuncAttributeMaxDynamicSharedMemorySize,
                             HGEMM_SMEM);
        cudaFuncSetAttribute(k_k3v2, cudaFuncAttributeMaxDynamicSharedMemorySize,
                             K3V_SMEM);
        cudaFuncSetAttribute(k_coeff2, cudaFuncAttributeMaxDynamicSharedMemorySize,
                             COEFF_SMEM);
        cudaFuncSetAttribute(k_attn_ln, cudaFuncAttributeMaxDynamicSharedMemorySize,
                             ATTNLN_SMEM);
        smem_set = 1;
    }

    dim3 tb32(32, 8);
    // 0. pack all weights (single launch) + biases
    int totW = 3 * NQ4 + 2 * NM4;
    k_w2hall<<<(totW + 255) / 256, 256>>>(Wq, Wk, Wv, W1, W2, pWqkvh, pW1h, pW2h);
    k_packb<<<12, 256>>>(bq, bk, bv, pBqkv);
    // 1. X (B,E,S) -> XTh (B,S,E) fp16
    k_transpose_in<<<dim3((Ss + 31) / 32, Ee / 32, Bb), tb32>>>(X);
    // 2. fused QKV projection (N=3072)
    k_hgemm<<<dim3(125, 24), 512, HGEMM_SMEM>>>(pXTh, pWqkvh, pBqkv, pQKV,
                                                Ee, 3072, 0, QKSCALE);
    // 3-8. attention path
    k_landmarks<<<BH * Mm, 64>>>();
    k_k2<<<BH, 128>>>();
    k_norm<<<1, 256>>>();
    k_inv<<<BH, 128>>>();
    k_k3v2<<<BH, 256, K3V_SMEM>>>();
    k_coeff2<<<BH, 256, COEFF_SMEM>>>();
    // 9. fused attn assembly + LN1 -> fp16 h1h
    k_attn_ln<<<dim3(50, Bb), 256, ATTNLN_SMEM>>>(g1, be1);
    // 10. MLP1 + GELU -> fp16 mid
    k_hgemm<<<dim3(125, 32), 512, HGEMM_SMEM>>>(pH1h, pW1h, b1, pMidh, Ee, MLPn, 1, 1.0f);
    // 11. MLP2 -> f32 h2
    k_hgemm<<<dim3(125, 8), 512, HGEMM_SMEM>>>(pMidh, pW2h, b2, pH2, MLPn, Ee, 2, 1.0f);
    // 12. LN2 stats
    k_lnstats<<<Bb * Ss, 256>>>();
    // 13. fused transpose + LN2 apply -> out (B,E,S)
    k_transpose_out_ln<<<dim3(Ee / 32, (Ss + 31) / 32, Bb), tb32>>>(out, g2, be2);
}